// round 1
// baseline (speedup 1.0000x reference)
#include <cuda_runtime.h>
#include <math.h>

#define NB    1024
#define SIN   256
#define SPR   128
#define HIDN  512

struct Params {
    const float* X;           // 0  (B,256,3)
    const float* T;           // 1  (B,128,3)
    const float* enc_in_w;    // 2  (9,3)
    const float* enc_in_b;    // 3  (9)
    const float* enc_out_w;   // 4  (3,3)
    const float* enc_out_b;   // 5  (3)
    const float* enc_ln1_w;   // 6  (256,3)
    const float* enc_ln1_b;   // 7
    const float* enc_lin1_w;  // 8  (512,3)
    const float* enc_lin1_b;  // 9  (512)
    const float* enc_lin2_w;  // 10 (3,512)
    const float* enc_lin2_b;  // 11 (3)
    const float* enc_ln2_w;   // 12
    const float* enc_ln2_b;   // 13
    const float* dec_a1_in_w; // 14
    const float* dec_a1_in_b; // 15
    const float* dec_a1_out_w;// 16
    const float* dec_a1_out_b;// 17
    const float* dec_ln1_w;   // 18 (128,3)
    const float* dec_ln1_b;   // 19
    const float* dec_a2_in_w; // 20
    const float* dec_a2_in_b; // 21
    const float* dec_a2_out_w;// 22
    const float* dec_a2_out_b;// 23
    const float* dec_lin1_w;  // 24
    const float* dec_lin1_b;  // 25
    const float* dec_lin2_w;  // 26
    const float* dec_lin2_b;  // 27
    const float* dec_ln3_w;   // 28
    const float* dec_ln3_b;   // 29
    float* out;               // (B,128,3)
};

// ---------- helpers ----------

__device__ __forceinline__ float block_sum(float v, float* red) {
    #pragma unroll
    for (int o = 16; o; o >>= 1) v += __shfl_xor_sync(0xffffffffu, v, o);
    int w = threadIdx.x >> 5;
    if ((threadIdx.x & 31) == 0) red[w] = v;
    __syncthreads();
    if (threadIdx.x < 32) {
        float x = (threadIdx.x < 8) ? red[threadIdx.x] : 0.f;
        #pragma unroll
        for (int o = 4; o; o >>= 1) x += __shfl_xor_sync(0xffffffffu, x, o);
        if (threadIdx.x == 0) red[0] = x;
    }
    __syncthreads();
    float r = red[0];
    __syncthreads();
    return r;
}

// LayerNorm over all nrows*3 elements of src (per-batch, axes (-2,-1) jointly).
__device__ __forceinline__ void layer_norm(const float* src, float* dst, int nrows,
                                           const float* w, const float* bb, float* red) {
    int t = threadIdx.x;
    float x0 = 0.f, x1 = 0.f, x2 = 0.f;
    if (t < nrows) { x0 = src[t*3]; x1 = src[t*3+1]; x2 = src[t*3+2]; }
    float n = (float)(nrows * 3);
    float mean = block_sum((t < nrows) ? (x0 + x1 + x2) : 0.f, red) / n;
    float d0 = x0 - mean, d1 = x1 - mean, d2 = x2 - mean;
    float var = block_sum((t < nrows) ? (d0*d0 + d1*d1 + d2*d2) : 0.f, red) / n;
    float rs = rsqrtf(var + 1e-5f);
    if (t < nrows) {
        dst[t*3+0] = d0 * rs * w[t*3+0] + bb[t*3+0];
        dst[t*3+1] = d1 * rs * w[t*3+1] + bb[t*3+1];
        dst[t*3+2] = d2 * rs * w[t*3+2] + bb[t*3+2];
    }
    __syncthreads();
}

// 3x3 projection: o = W(3x3 row-major) * x + b
__device__ __forceinline__ void proj3(const float* w, const float* bias,
                                      float x0, float x1, float x2,
                                      float& o0, float& o1, float& o2) {
    o0 = fmaf(w[0], x0, fmaf(w[1], x1, fmaf(w[2], x2, bias[0])));
    o1 = fmaf(w[3], x0, fmaf(w[4], x1, fmaf(w[5], x2, bias[1])));
    o2 = fmaf(w[6], x0, fmaf(w[7], x1, fmaf(w[8], x2, bias[2])));
}

// Online-softmax attention over keys [j0,j1). kv packed as float4 pairs.
// MASK: add +1.0 where j <= maskRow (reference adds tril(ones), not -inf!)
template<bool MASK>
__device__ __forceinline__ void attn_online(const float4* kv, int j0, int j1, int maskRow,
                                            float q0, float q1, float q2,
                                            float& m, float& l,
                                            float& a0, float& a1, float& a2) {
    const float scale = 0.5773502691896258f; // 1/sqrt(3)
    #pragma unroll 4
    for (int j = j0; j < j1; ++j) {
        float4 k = kv[2*j];
        float4 v = kv[2*j+1];
        float s = (q0*k.x + q1*k.y + q2*k.z) * scale;
        if (MASK) s += (j <= maskRow) ? 1.0f : 0.0f;
        if (s > m) {
            float c = __expf(m - s);
            l *= c; a0 *= c; a1 *= c; a2 *= c;
            m = s;
        }
        float p = __expf(s - m);
        l += p;
        a0 = fmaf(p, v.x, a0);
        a1 = fmaf(p, v.y, a1);
        a2 = fmaf(p, v.z, a2);
    }
}

// Load FFN weights packed: wff[2h]=(w1[h][0..2], b1[h]), wff[2h+1]=(w2[0][h],w2[1][h],w2[2][h],0)
__device__ __forceinline__ void load_wff(float4* s_wff, const float* w1, const float* b1,
                                         const float* w2) {
    for (int h = threadIdx.x; h < HIDN; h += 256) {
        s_wff[2*h]   = make_float4(w1[h*3], w1[h*3+1], w1[h*3+2], b1[h]);
        s_wff[2*h+1] = make_float4(w2[h], w2[HIDN + h], w2[2*HIDN + h], 0.f);
    }
    __syncthreads();
}

__device__ __forceinline__ void ffn_range(const float4* s_wff, float x0, float x1, float x2,
                                          int h0, int h1,
                                          float& a0, float& a1, float& a2) {
    a0 = 0.f; a1 = 0.f; a2 = 0.f;
    #pragma unroll 8
    for (int h = h0; h < h1; ++h) {
        float4 w1 = s_wff[2*h];
        float4 w2 = s_wff[2*h+1];
        float tt = fmaxf(fmaf(w1.x, x0, fmaf(w1.y, x1, fmaf(w1.z, x2, w1.w))), 0.f);
        a0 = fmaf(tt, w2.x, a0);
        a1 = fmaf(tt, w2.y, a1);
        a2 = fmaf(tt, w2.z, a2);
    }
}

// pos_enc row s: first 3 sin columns, invf[e] = 10000^(-2e/256).
// fp32 argument, double-precision sin -> correctly-rounded fp32 (matches JAX f32 sin ~1ulp)
__device__ __forceinline__ void pos3(int s, float& p0, float& p1, float& p2) {
    float f1 = (float)pow(10000.0, -2.0/256.0);
    float f2 = (float)pow(10000.0, -4.0/256.0);
    float a0 = (float)s;
    float a1 = (float)s * f1;
    float a2 = (float)s * f2;
    p0 = (float)sin((double)a0);
    p1 = (float)sin((double)a1);
    p2 = (float)sin((double)a2);
}

// ---------- fused kernel: one CTA = one batch, whole network ----------

__global__ void __launch_bounds__(256)
fused_transformer_kernel(Params P) {
    __shared__ float4 s_kv[SIN * 2];      // packed K/V   (8 KB)
    __shared__ float4 s_wff[HIDN * 2];    // FFN weights  (16 KB)
    __shared__ float4 s_part[SIN * 2];    // split partials (8 KB)
    __shared__ float  s_bufA[SIN * 3];    // pX / pT / final
    __shared__ float  s_bufR[SIN * 3];    // pre-LN residual
    __shared__ float  s_x2[SIN * 3];      // x2 / x3
    __shared__ float  s_enc[SIN * 3];     // encoder output
    __shared__ float  s_red[32];

    const int b = blockIdx.x;
    const int t = threadIdx.x;

    float pe0, pe1, pe2;
    pos3(t, pe0, pe1, pe2);

    // ================= ENCODER =================
    // E1: pX = X + pos_enc
    {
        const float* xr = P.X + ((size_t)b * SIN + t) * 3;
        s_bufA[t*3+0] = xr[0] + pe0;
        s_bufA[t*3+1] = xr[1] + pe1;
        s_bufA[t*3+2] = xr[2] + pe2;
    }
    __syncthreads();

    // E2: QKV projections. q in regs, k/v packed into smem.
    float q0, q1, q2;
    {
        float x0 = s_bufA[t*3], x1 = s_bufA[t*3+1], x2v = s_bufA[t*3+2];
        proj3(P.enc_in_w,      P.enc_in_b,     x0, x1, x2v, q0, q1, q2);
        float k0,k1,k2, v0,v1,v2;
        proj3(P.enc_in_w + 9,  P.enc_in_b + 3, x0, x1, x2v, k0, k1, k2);
        proj3(P.enc_in_w + 18, P.enc_in_b + 6, x0, x1, x2v, v0, v1, v2);
        s_kv[2*t]   = make_float4(k0, k1, k2, 0.f);
        s_kv[2*t+1] = make_float4(v0, v1, v2, 0.f);
    }
    __syncthreads();

    // E3: self-attention (256 keys) + out proj + residual
    {
        float m = -1e30f, l = 0.f, a0 = 0.f, a1 = 0.f, a2 = 0.f;
        attn_online<false>(s_kv, 0, SIN, 0, q0, q1, q2, m, l, a0, a1, a2);
        float inv = 1.0f / l;
        float r0, r1, r2;
        proj3(P.enc_out_w, P.enc_out_b, a0*inv, a1*inv, a2*inv, r0, r1, r2);
        s_bufR[t*3+0] = r0 + s_bufA[t*3+0];
        s_bufR[t*3+1] = r1 + s_bufA[t*3+1];
        s_bufR[t*3+2] = r2 + s_bufA[t*3+2];
    }
    __syncthreads();

    // E4: LN1 -> x2
    layer_norm(s_bufR, s_x2, SIN, P.enc_ln1_w, P.enc_ln1_b, s_red);

    // E5: FFN + residual, LN2 -> enc_out
    load_wff(s_wff, P.enc_lin1_w, P.enc_lin1_b, P.enc_lin2_w);
    {
        float x0 = s_x2[t*3], x1 = s_x2[t*3+1], x2v = s_x2[t*3+2];
        float a0, a1, a2;
        ffn_range(s_wff, x0, x1, x2v, 0, HIDN, a0, a1, a2);
        s_bufR[t*3+0] = a0 + P.enc_lin2_b[0] + x0;
        s_bufR[t*3+1] = a1 + P.enc_lin2_b[1] + x1;
        s_bufR[t*3+2] = a2 + P.enc_lin2_b[2] + x2v;
    }
    __syncthreads();
    layer_norm(s_bufR, s_enc, SIN, P.enc_ln2_w, P.enc_ln2_b, s_red);

    // ================= DECODER =================
    // D1/D2: pT + self-attn QKV
    float dq0 = 0.f, dq1 = 0.f, dq2 = 0.f;
    if (t < SPR) {
        const float* tr = P.T + ((size_t)b * SPR + t) * 3;
        float x0 = tr[0] + pe0, x1 = tr[1] + pe1, x2v = tr[2] + pe2;
        s_bufA[t*3+0] = x0; s_bufA[t*3+1] = x1; s_bufA[t*3+2] = x2v;
        proj3(P.dec_a1_in_w,      P.dec_a1_in_b,     x0, x1, x2v, dq0, dq1, dq2);
        float k0,k1,k2, v0,v1,v2;
        proj3(P.dec_a1_in_w + 9,  P.dec_a1_in_b + 3, x0, x1, x2v, k0, k1, k2);
        proj3(P.dec_a1_in_w + 18, P.dec_a1_in_b + 6, x0, x1, x2v, v0, v1, v2);
        s_kv[2*t]   = make_float4(k0, k1, k2, 0.f);
        s_kv[2*t+1] = make_float4(v0, v1, v2, 0.f);
    }
    __syncthreads();

    // D3: self-attn, mask = +1.0 on j<=t (tril(ones) ADDED to scores)
    if (t < SPR) {
        float m = -1e30f, l = 0.f, a0 = 0.f, a1 = 0.f, a2 = 0.f;
        attn_online<true>(s_kv, 0, SPR, t, dq0, dq1, dq2, m, l, a0, a1, a2);
        float inv = 1.0f / l;
        float r0, r1, r2;
        proj3(P.dec_a1_out_w, P.dec_a1_out_b, a0*inv, a1*inv, a2*inv, r0, r1, r2);
        s_bufR[t*3+0] = r0 + s_bufA[t*3+0];
        s_bufR[t*3+1] = r1 + s_bufA[t*3+1];
        s_bufR[t*3+2] = r2 + s_bufA[t*3+2];
    }
    __syncthreads();
    layer_norm(s_bufR, s_x2, SPR, P.dec_ln1_w, P.dec_ln1_b, s_red);

    // D4: cross-attn K/V from enc_out (256 rows, all threads)
    {
        float x0 = s_enc[t*3], x1 = s_enc[t*3+1], x2v = s_enc[t*3+2];
        float k0,k1,k2, v0,v1,v2;
        proj3(P.dec_a2_in_w + 9,  P.dec_a2_in_b + 3, x0, x1, x2v, k0, k1, k2);
        proj3(P.dec_a2_in_w + 18, P.dec_a2_in_b + 6, x0, x1, x2v, v0, v1, v2);
        s_kv[2*t]   = make_float4(k0, k1, k2, 0.f);
        s_kv[2*t+1] = make_float4(v0, v1, v2, 0.f);
    }
    __syncthreads();

    // D5: cross-attn split over 2 key-halves (all 256 threads busy), flash-merge
    {
        int row = t & 127, half = t >> 7;
        float cq0, cq1, cq2;
        proj3(P.dec_a2_in_w, P.dec_a2_in_b,
              s_x2[row*3], s_x2[row*3+1], s_x2[row*3+2], cq0, cq1, cq2);
        float m = -1e30f, l = 0.f, a0 = 0.f, a1 = 0.f, a2 = 0.f;
        attn_online<false>(s_kv, half * 128, half * 128 + 128, 0,
                           cq0, cq1, cq2, m, l, a0, a1, a2);
        s_part[2*t]   = make_float4(m, l, a0, a1);
        s_part[2*t+1] = make_float4(a2, 0.f, 0.f, 0.f);
    }
    __syncthreads();
    if (t < SPR) {
        float4 pA  = s_part[2*t],        pA2 = s_part[2*t+1];
        float4 pB  = s_part[2*(t+128)],  pB2 = s_part[2*(t+128)+1];
        float M  = fmaxf(pA.x, pB.x);
        float cA = __expf(pA.x - M), cB = __expf(pB.x - M);
        float l  = pA.y * cA + pB.y * cB;
        float a0 = pA.z * cA + pB.z * cB;
        float a1 = pA.w * cA + pB.w * cB;
        float a2 = pA2.x * cA + pB2.x * cB;
        float inv = 1.0f / l;
        float r0, r1, r2;
        proj3(P.dec_a2_out_w, P.dec_a2_out_b, a0*inv, a1*inv, a2*inv, r0, r1, r2);
        s_bufR[t*3+0] = r0 + s_x2[t*3+0];
        s_bufR[t*3+1] = r1 + s_x2[t*3+1];
        s_bufR[t*3+2] = r2 + s_x2[t*3+2];
    }
    __syncthreads();
    layer_norm(s_bufR, s_x2, SPR, P.dec_ln1_w, P.dec_ln1_b, s_red);  // x3

    // D6: FFN split over hidden dim (2 halves), combine, LN3, write out
    load_wff(s_wff, P.dec_lin1_w, P.dec_lin1_b, P.dec_lin2_w);
    {
        int row = t & 127, half = t >> 7;
        float x0 = s_x2[row*3], x1 = s_x2[row*3+1], x2v = s_x2[row*3+2];
        float a0, a1, a2;
        ffn_range(s_wff, x0, x1, x2v, half * 256, half * 256 + 256, a0, a1, a2);
        s_part[2*t] = make_float4(a0, a1, a2, 0.f);
    }
    __syncthreads();
    if (t < SPR) {
        float4 pA = s_part[2*t], pB = s_part[2*(t+128)];
        s_bufR[t*3+0] = pA.x + pB.x + P.dec_lin2_b[0] + s_x2[t*3+0];
        s_bufR[t*3+1] = pA.y + pB.y + P.dec_lin2_b[1] + s_x2[t*3+1];
        s_bufR[t*3+2] = pA.z + pB.z + P.dec_lin2_b[2] + s_x2[t*3+2];
    }
    __syncthreads();
    layer_norm(s_bufR, s_bufA, SPR, P.dec_ln3_w, P.dec_ln3_b, s_red);

    if (t < SPR) {
        float* o = P.out + ((size_t)b * SPR + t) * 3;
        o[0] = s_bufA[t*3+0];
        o[1] = s_bufA[t*3+1];
        o[2] = s_bufA[t*3+2];
    }
}

extern "C" void kernel_launch(void* const* d_in, const int* in_sizes, int n_in,
                              void* d_out, int out_size) {
    (void)in_sizes; (void)n_in; (void)out_size;
    Params P;
    P.X            = (const float*)d_in[0];
    P.T            = (const float*)d_in[1];
    P.enc_in_w     = (const float*)d_in[2];
    P.enc_in_b     = (const float*)d_in[3];
    P.enc_out_w    = (const float*)d_in[4];
    P.enc_out_b    = (const float*)d_in[5];
    P.enc_ln1_w    = (const float*)d_in[6];
    P.enc_ln1_b    = (const float*)d_in[7];
    P.enc_lin1_w   = (const float*)d_in[8];
    P.enc_lin1_b   = (const float*)d_in[9];
    P.enc_lin2_w   = (const float*)d_in[10];
    P.enc_lin2_b   = (const float*)d_in[11];
    P.enc_ln2_w    = (const float*)d_in[12];
    P.enc_ln2_b    = (const float*)d_in[13];
    P.dec_a1_in_w  = (const float*)d_in[14];
    P.dec_a1_in_b  = (const float*)d_in[15];
    P.dec_a1_out_w = (const float*)d_in[16];
    P.dec_a1_out_b = (const float*)d_in[17];
    P.dec_ln1_w    = (const float*)d_in[18];
    P.dec_ln1_b    = (const float*)d_in[19];
    P.dec_a2_in_w  = (const float*)d_in[20];
    P.dec_a2_in_b  = (const float*)d_in[21];
    P.dec_a2_out_w = (const float*)d_in[22];
    P.dec_a2_out_b = (const float*)d_in[23];
    P.dec_lin1_w   = (const float*)d_in[24];
    P.dec_lin1_b   = (const float*)d_in[25];
    P.dec_lin2_w   = (const float*)d_in[26];
    P.dec_lin2_b   = (const float*)d_in[27];
    P.dec_ln3_w    = (const float*)d_in[28];
    P.dec_ln3_b    = (const float*)d_in[29];
    P.out          = (float*)d_out;

    fused_transformer_kernel<<<NB, 256>>>(P);
}

// round 2
// speedup vs baseline: 1.0931x; 1.0931x over previous
#include <cuda_runtime.h>
#include <math.h>

#define NB    1024
#define SIN   256
#define SPR   128
#define HIDN  512

// 1/sqrt(3) * log2(e): fold scores into exp2 domain
#define C_SCALE 0.83294064f
// exp(1): additive mask of +1.0 becomes multiplicative e after exp
#define MASK_E  2.718281828459045f

struct Params {
    const float* X;           const float* T;
    const float* enc_in_w;    const float* enc_in_b;
    const float* enc_out_w;   const float* enc_out_b;
    const float* enc_ln1_w;   const float* enc_ln1_b;
    const float* enc_lin1_w;  const float* enc_lin1_b;
    const float* enc_lin2_w;  const float* enc_lin2_b;
    const float* enc_ln2_w;   const float* enc_ln2_b;
    const float* dec_a1_in_w; const float* dec_a1_in_b;
    const float* dec_a1_out_w;const float* dec_a1_out_b;
    const float* dec_ln1_w;   const float* dec_ln1_b;
    const float* dec_a2_in_w; const float* dec_a2_in_b;
    const float* dec_a2_out_w;const float* dec_a2_out_b;
    const float* dec_lin1_w;  const float* dec_lin1_b;
    const float* dec_lin2_w;  const float* dec_lin2_b;
    const float* dec_ln3_w;   const float* dec_ln3_b;
    float* out;
};

__device__ __forceinline__ float ex2f(float x) {
    float y; asm("ex2.approx.ftz.f32 %0, %1;" : "=f"(y) : "f"(x)); return y;
}

__device__ __forceinline__ float block_sum(float v, float* red) {
    #pragma unroll
    for (int o = 16; o; o >>= 1) v += __shfl_xor_sync(0xffffffffu, v, o);
    int w = threadIdx.x >> 5;
    if ((threadIdx.x & 31) == 0) red[w] = v;
    __syncthreads();
    if (threadIdx.x < 32) {
        float x = (threadIdx.x < 8) ? red[threadIdx.x] : 0.f;
        #pragma unroll
        for (int o = 4; o; o >>= 1) x += __shfl_xor_sync(0xffffffffu, x, o);
        if (threadIdx.x == 0) red[0] = x;
    }
    __syncthreads();
    float r = red[0];
    __syncthreads();
    return r;
}

// LN over all nrows*3 elems jointly (axes (-2,-1)), per-(s,e) affine.
__device__ __forceinline__ void layer_norm(const float* src, float* dst, int nrows,
                                           const float* w, const float* bb, float* red) {
    int t = threadIdx.x;
    float x0 = 0.f, x1 = 0.f, x2 = 0.f;
    if (t < nrows) { x0 = src[t*3]; x1 = src[t*3+1]; x2 = src[t*3+2]; }
    float n = (float)(nrows * 3);
    float mean = block_sum((t < nrows) ? (x0 + x1 + x2) : 0.f, red) / n;
    float d0 = x0 - mean, d1 = x1 - mean, d2 = x2 - mean;
    float var = block_sum((t < nrows) ? (d0*d0 + d1*d1 + d2*d2) : 0.f, red) / n;
    float rs = rsqrtf(var + 1e-5f);
    if (t < nrows) {
        dst[t*3+0] = d0 * rs * w[t*3+0] + bb[t*3+0];
        dst[t*3+1] = d1 * rs * w[t*3+1] + bb[t*3+1];
        dst[t*3+2] = d2 * rs * w[t*3+2] + bb[t*3+2];
    }
    __syncthreads();
}

__device__ __forceinline__ void proj3(const float* w, const float* bias,
                                      float x0, float x1, float x2,
                                      float& o0, float& o1, float& o2) {
    o0 = fmaf(w[0], x0, fmaf(w[1], x1, fmaf(w[2], x2, bias[0])));
    o1 = fmaf(w[3], x0, fmaf(w[4], x1, fmaf(w[5], x2, bias[1])));
    o2 = fmaf(w[6], x0, fmaf(w[7], x1, fmaf(w[8], x2, bias[2])));
}

// No-max softmax accumulation: q is pre-scaled into exp2 domain.
template<bool MASK>
__device__ __forceinline__ void attn_acc(const float4* kv, int j0, int j1, int maskRow,
                                         float q0, float q1, float q2,
                                         float& l, float& a0, float& a1, float& a2) {
    #pragma unroll 4
    for (int j = j0; j < j1; ++j) {
        float4 k = kv[2*j];
        float4 v = kv[2*j+1];
        float s = q0 * k.x;
        s = fmaf(q1, k.y, s);
        s = fmaf(q2, k.z, s);
        float p = ex2f(s);
        if (MASK) p *= (j <= maskRow) ? MASK_E : 1.0f;
        l += p;
        a0 = fmaf(p, v.x, a0);
        a1 = fmaf(p, v.y, a1);
        a2 = fmaf(p, v.z, a2);
    }
}

__device__ __forceinline__ void load_wff(float4* s_wff, const float* w1, const float* b1,
                                         const float* w2) {
    for (int h = threadIdx.x; h < HIDN; h += 256) {
        s_wff[2*h]   = make_float4(w1[h*3], w1[h*3+1], w1[h*3+2], b1[h]);
        s_wff[2*h+1] = make_float4(w2[h], w2[HIDN + h], w2[2*HIDN + h], 0.f);
    }
    __syncthreads();
}

__device__ __forceinline__ void ffn_range(const float4* s_wff, float x0, float x1, float x2,
                                          int h0, int h1,
                                          float& a0, float& a1, float& a2) {
    a0 = 0.f; a1 = 0.f; a2 = 0.f;
    #pragma unroll 4
    for (int h = h0; h < h1; ++h) {
        float4 w1 = s_wff[2*h];
        float4 w2 = s_wff[2*h+1];
        float tt = fmaxf(fmaf(w1.x, x0, fmaf(w1.y, x1, fmaf(w1.z, x2, w1.w))), 0.f);
        a0 = fmaf(tt, w2.x, a0);
        a1 = fmaf(tt, w2.y, a1);
        a2 = fmaf(tt, w2.z, a2);
    }
}

// pos_enc row s: first 3 sin columns, invf[e] = 10000^(-2e/256)
__device__ __forceinline__ void pos3(int s, float& p0, float& p1, float& p2) {
    float f1 = (float)pow(10000.0, -2.0/256.0);
    float f2 = (float)pow(10000.0, -4.0/256.0);
    float a0 = (float)s;
    float a1 = (float)s * f1;
    float a2 = (float)s * f2;
    p0 = (float)sin((double)a0);
    p1 = (float)sin((double)a1);
    p2 = (float)sin((double)a2);
}

// One CTA = one batch, whole network. 7 CTAs/SM -> single wave for grid 1024.
__global__ void __launch_bounds__(256, 7)
fused_transformer_kernel(Params P) {
    // 16 KB union: [wff 16KB] OR [kv 8KB | part 2KB | spare]
    __shared__ __align__(16) float4 s_U[1024];
    __shared__ float s_bufA[SIN * 3];
    __shared__ float s_bufR[SIN * 3];
    __shared__ float s_x2[SIN * 3];
    __shared__ float s_enc[SIN * 3];
    __shared__ float s_red[32];

    float4* const u_kv   = s_U;        // 256 keys * 2 float4
    float4* const u_part = s_U + 512;  // 128 partial float4 (l,a0,a1,a2)
    float4* const u_wff  = s_U;        // 512 * 2 float4

    const int b = blockIdx.x;
    const int t = threadIdx.x;

    float pe0, pe1, pe2;
    pos3(t, pe0, pe1, pe2);

    // ================= ENCODER =================
    {
        const float* xr = P.X + ((size_t)b * SIN + t) * 3;
        s_bufA[t*3+0] = xr[0] + pe0;
        s_bufA[t*3+1] = xr[1] + pe1;
        s_bufA[t*3+2] = xr[2] + pe2;
    }
    __syncthreads();

    float q0, q1, q2;
    {
        float x0 = s_bufA[t*3], x1 = s_bufA[t*3+1], x2v = s_bufA[t*3+2];
        proj3(P.enc_in_w,      P.enc_in_b,     x0, x1, x2v, q0, q1, q2);
        float k0,k1,k2, v0,v1,v2;
        proj3(P.enc_in_w + 9,  P.enc_in_b + 3, x0, x1, x2v, k0, k1, k2);
        proj3(P.enc_in_w + 18, P.enc_in_b + 6, x0, x1, x2v, v0, v1, v2);
        u_kv[2*t]   = make_float4(k0, k1, k2, 0.f);
        u_kv[2*t+1] = make_float4(v0, v1, v2, 0.f);
        q0 *= C_SCALE; q1 *= C_SCALE; q2 *= C_SCALE;
    }
    __syncthreads();

    // self-attention over 256 keys (no max-subtraction: scores bounded)
    {
        float l = 0.f, a0 = 0.f, a1 = 0.f, a2 = 0.f;
        attn_acc<false>(u_kv, 0, SIN, 0, q0, q1, q2, l, a0, a1, a2);
        float inv = 1.0f / l;
        float r0, r1, r2;
        proj3(P.enc_out_w, P.enc_out_b, a0*inv, a1*inv, a2*inv, r0, r1, r2);
        s_bufR[t*3+0] = r0 + s_bufA[t*3+0];
        s_bufR[t*3+1] = r1 + s_bufA[t*3+1];
        s_bufR[t*3+2] = r2 + s_bufA[t*3+2];
    }
    __syncthreads();

    layer_norm(s_bufR, s_x2, SIN, P.enc_ln1_w, P.enc_ln1_b, s_red);

    load_wff(u_wff, P.enc_lin1_w, P.enc_lin1_b, P.enc_lin2_w);
    {
        float x0 = s_x2[t*3], x1 = s_x2[t*3+1], x2v = s_x2[t*3+2];
        float a0, a1, a2;
        ffn_range(u_wff, x0, x1, x2v, 0, HIDN, a0, a1, a2);
        s_bufR[t*3+0] = a0 + P.enc_lin2_b[0] + x0;
        s_bufR[t*3+1] = a1 + P.enc_lin2_b[1] + x1;
        s_bufR[t*3+2] = a2 + P.enc_lin2_b[2] + x2v;
    }
    __syncthreads();
    layer_norm(s_bufR, s_enc, SIN, P.enc_ln2_w, P.enc_ln2_b, s_red);

    // ================= DECODER =================
    // pT + self-attn K/V (rows 0..127)
    if (t < SPR) {
        const float* tr = P.T + ((size_t)b * SPR + t) * 3;
        float x0 = tr[0] + pe0, x1 = tr[1] + pe1, x2v = tr[2] + pe2;
        s_bufA[t*3+0] = x0; s_bufA[t*3+1] = x1; s_bufA[t*3+2] = x2v;
        float k0,k1,k2, v0,v1,v2;
        proj3(P.dec_a1_in_w + 9,  P.dec_a1_in_b + 3, x0, x1, x2v, k0, k1, k2);
        proj3(P.dec_a1_in_w + 18, P.dec_a1_in_b + 6, x0, x1, x2v, v0, v1, v2);
        u_kv[2*t]   = make_float4(k0, k1, k2, 0.f);
        u_kv[2*t+1] = make_float4(v0, v1, v2, 0.f);
    }
    __syncthreads();

    // decoder self-attn: keys split across thread halves (64 each), all warps busy.
    // mask: reference ADDS tril(ones) -> multiply p by e where j <= row.
    {
        int row = t & 127, half = t >> 7;
        float x0 = s_bufA[row*3], x1 = s_bufA[row*3+1], x2v = s_bufA[row*3+2];
        float dq0, dq1, dq2;
        proj3(P.dec_a1_in_w, P.dec_a1_in_b, x0, x1, x2v, dq0, dq1, dq2);
        dq0 *= C_SCALE; dq1 *= C_SCALE; dq2 *= C_SCALE;
        float l = 0.f, a0 = 0.f, a1 = 0.f, a2 = 0.f;
        attn_acc<true>(u_kv, half * 64, half * 64 + 64, row, dq0, dq1, dq2, l, a0, a1, a2);
        if (half) u_part[row] = make_float4(l, a0, a1, a2);
        __syncthreads();
        if (t < SPR) {
            float4 pb = u_part[row];
            l += pb.x; a0 += pb.y; a1 += pb.z; a2 += pb.w;
            float inv = 1.0f / l;
            float r0, r1, r2;
            proj3(P.dec_a1_out_w, P.dec_a1_out_b, a0*inv, a1*inv, a2*inv, r0, r1, r2);
            s_bufR[t*3+0] = r0 + s_bufA[t*3+0];
            s_bufR[t*3+1] = r1 + s_bufA[t*3+1];
            s_bufR[t*3+2] = r2 + s_bufA[t*3+2];
        }
    }
    __syncthreads();
    layer_norm(s_bufR, s_x2, SPR, P.dec_ln1_w, P.dec_ln1_b, s_red);

    // cross-attn K/V from enc_out (256 keys, all threads)
    {
        float x0 = s_enc[t*3], x1 = s_enc[t*3+1], x2v = s_enc[t*3+2];
        float k0,k1,k2, v0,v1,v2;
        proj3(P.dec_a2_in_w + 9,  P.dec_a2_in_b + 3, x0, x1, x2v, k0, k1, k2);
        proj3(P.dec_a2_in_w + 18, P.dec_a2_in_b + 6, x0, x1, x2v, v0, v1, v2);
        u_kv[2*t]   = make_float4(k0, k1, k2, 0.f);
        u_kv[2*t+1] = make_float4(v0, v1, v2, 0.f);
    }
    __syncthreads();

    // cross-attn: 128 queries x 256 keys split across thread halves
    {
        int row = t & 127, half = t >> 7;
        float cq0, cq1, cq2;
        proj3(P.dec_a2_in_w, P.dec_a2_in_b,
              s_x2[row*3], s_x2[row*3+1], s_x2[row*3+2], cq0, cq1, cq2);
        cq0 *= C_SCALE; cq1 *= C_SCALE; cq2 *= C_SCALE;
        float l = 0.f, a0 = 0.f, a1 = 0.f, a2 = 0.f;
        attn_acc<false>(u_kv, half * 128, half * 128 + 128, 0, cq0, cq1, cq2, l, a0, a1, a2);
        if (half) u_part[row] = make_float4(l, a0, a1, a2);
        __syncthreads();
        if (t < SPR) {
            float4 pb = u_part[row];
            l += pb.x; a0 += pb.y; a1 += pb.z; a2 += pb.w;
            float inv = 1.0f / l;
            float r0, r1, r2;
            proj3(P.dec_a2_out_w, P.dec_a2_out_b, a0*inv, a1*inv, a2*inv, r0, r1, r2);
            s_bufR[t*3+0] = r0 + s_x2[t*3+0];
            s_bufR[t*3+1] = r1 + s_x2[t*3+1];
            s_bufR[t*3+2] = r2 + s_x2[t*3+2];
        }
    }
    __syncthreads();
    layer_norm(s_bufR, s_x2, SPR, P.dec_ln1_w, P.dec_ln1_b, s_red);  // x3

    // decoder FFN split over hidden halves; partials into s_bufA (pT dead now)
    load_wff(u_wff, P.dec_lin1_w, P.dec_lin1_b, P.dec_lin2_w);
    {
        int row = t & 127, half = t >> 7;
        float x0 = s_x2[row*3], x1 = s_x2[row*3+1], x2v = s_x2[row*3+2];
        float a0, a1, a2;
        ffn_range(u_wff, x0, x1, x2v, half * 256, half * 256 + 256, a0, a1, a2);
        s_bufA[t*3+0] = a0; s_bufA[t*3+1] = a1; s_bufA[t*3+2] = a2;
    }
    __syncthreads();
    if (t < SPR) {
        s_bufR[t*3+0] = s_bufA[t*3+0] + s_bufA[(t+128)*3+0] + P.dec_lin2_b[0] + s_x2[t*3+0];
        s_bufR[t*3+1] = s_bufA[t*3+1] + s_bufA[(t+128)*3+1] + P.dec_lin2_b[1] + s_x2[t*3+1];
        s_bufR[t*3+2] = s_bufA[t*3+2] + s_bufA[(t+128)*3+2] + P.dec_lin2_b[2] + s_x2[t*3+2];
    }
    __syncthreads();
    layer_norm(s_bufR, s_bufA, SPR, P.dec_ln3_w, P.dec_ln3_b, s_red);

    if (t < SPR) {
        float* o = P.out + ((size_t)b * SPR + t) * 3;
        o[0] = s_bufA[t*3+0];
        o[1] = s_bufA[t*3+1];
        o[2] = s_bufA[t*3+2];
    }
}

extern "C" void kernel_launch(void* const* d_in, const int* in_sizes, int n_in,
                              void* d_out, int out_size) {
    (void)in_sizes; (void)n_in; (void)out_size;
    Params P;
    P.X            = (const float*)d_in[0];
    P.T            = (const float*)d_in[1];
    P.enc_in_w     = (const float*)d_in[2];
    P.enc_in_b     = (const float*)d_in[3];
    P.enc_out_w    = (const float*)d_in[4];
    P.enc_out_b    = (const float*)d_in[5];
    P.enc_ln1_w    = (const float*)d_in[6];
    P.enc_ln1_b    = (const float*)d_in[7];
    P.enc_lin1_w   = (const float*)d_in[8];
    P.enc_lin1_b   = (const float*)d_in[9];
    P.enc_lin2_w   = (const float*)d_in[10];
    P.enc_lin2_b   = (const float*)d_in[11];
    P.enc_ln2_w    = (const float*)d_in[12];
    P.enc_ln2_b    = (const float*)d_in[13];
    P.dec_a1_in_w  = (const float*)d_in[14];
    P.dec_a1_in_b  = (const float*)d_in[15];
    P.dec_a1_out_w = (const float*)d_in[16];
    P.dec_a1_out_b = (const float*)d_in[17];
    P.dec_ln1_w    = (const float*)d_in[18];
    P.dec_ln1_b    = (const float*)d_in[19];
    P.dec_a2_in_w  = (const float*)d_in[20];
    P.dec_a2_in_b  = (const float*)d_in[21];
    P.dec_a2_out_w = (const float*)d_in[22];
    P.dec_a2_out_b = (const float*)d_in[23];
    P.dec_lin1_w   = (const float*)d_in[24];
    P.dec_lin1_b   = (const float*)d_in[25];
    P.dec_lin2_w   = (const float*)d_in[26];
    P.dec_lin2_b   = (const float*)d_in[27];
    P.dec_ln3_w    = (const float*)d_in[28];
    P.dec_ln3_b    = (const float*)d_in[29];
    P.out          = (float*)d_out;

    fused_transformer_kernel<<<NB, 256>>>(P);
}

// round 3
// speedup vs baseline: 1.8641x; 1.7053x over previous
#include <cuda_runtime.h>
#include <math.h>

#define NB    1024
#define SIN   256
#define SPR   128
#define HIDN  512

// 1/sqrt(3) * log2(e): fold scores into exp2 domain
#define C_SCALE 0.83294064f
// exp(1): additive mask of +1.0 becomes multiplicative e after exp
#define MASK_E  2.7182818f

struct Params {
    const float* X;           const float* T;
    const float* enc_in_w;    const float* enc_in_b;
    const float* enc_out_w;   const float* enc_out_b;
    const float* enc_ln1_w;   const float* enc_ln1_b;
    const float* enc_lin1_w;  const float* enc_lin1_b;
    const float* enc_lin2_w;  const float* enc_lin2_b;
    const float* enc_ln2_w;   const float* enc_ln2_b;
    const float* dec_a1_in_w; const float* dec_a1_in_b;
    const float* dec_a1_out_w;const float* dec_a1_out_b;
    const float* dec_ln1_w;   const float* dec_ln1_b;
    const float* dec_a2_in_w; const float* dec_a2_in_b;
    const float* dec_a2_out_w;const float* dec_a2_out_b;
    const float* dec_lin1_w;  const float* dec_lin1_b;
    const float* dec_lin2_w;  const float* dec_lin2_b;
    const float* dec_ln3_w;   const float* dec_ln3_b;
    float* out;
};

__device__ __forceinline__ float ex2f(float x) {
    float y; asm("ex2.approx.ftz.f32 %0, %1;" : "=f"(y) : "f"(x)); return y;
}
__device__ __forceinline__ float rcpf(float x) {
    float y; asm("rcp.approx.ftz.f32 %0, %1;" : "=f"(y) : "f"(x)); return y;
}

__device__ __forceinline__ float block_sum(float v, float* red) {
    #pragma unroll
    for (int o = 16; o; o >>= 1) v += __shfl_xor_sync(0xffffffffu, v, o);
    int w = threadIdx.x >> 5;
    if ((threadIdx.x & 31) == 0) red[w] = v;
    __syncthreads();
    if (threadIdx.x < 32) {
        float x = (threadIdx.x < 8) ? red[threadIdx.x] : 0.f;
        #pragma unroll
        for (int o = 4; o; o >>= 1) x += __shfl_xor_sync(0xffffffffu, x, o);
        if (threadIdx.x == 0) red[0] = x;
    }
    __syncthreads();
    float r = red[0];
    __syncthreads();
    return r;
}

// LN over all nrows*3 elems jointly (axes (-2,-1)), per-(s,e) affine.
__device__ __forceinline__ void layer_norm(const float* src, float* dst, int nrows,
                                           const float* w, const float* bb, float* red) {
    int t = threadIdx.x;
    float x0 = 0.f, x1 = 0.f, x2 = 0.f;
    if (t < nrows) { x0 = src[t*3]; x1 = src[t*3+1]; x2 = src[t*3+2]; }
    float n = (float)(nrows * 3);
    float mean = block_sum((t < nrows) ? (x0 + x1 + x2) : 0.f, red) / n;
    float d0 = x0 - mean, d1 = x1 - mean, d2 = x2 - mean;
    float var = block_sum((t < nrows) ? (d0*d0 + d1*d1 + d2*d2) : 0.f, red) / n;
    float rs = rsqrtf(var + 1e-5f);
    if (t < nrows) {
        dst[t*3+0] = d0 * rs * w[t*3+0] + bb[t*3+0];
        dst[t*3+1] = d1 * rs * w[t*3+1] + bb[t*3+1];
        dst[t*3+2] = d2 * rs * w[t*3+2] + bb[t*3+2];
    }
    __syncthreads();
}

__device__ __forceinline__ void proj3(const float* w, const float* bias,
                                      float x0, float x1, float x2,
                                      float& o0, float& o1, float& o2) {
    o0 = fmaf(w[0], x0, fmaf(w[1], x1, fmaf(w[2], x2, bias[0])));
    o1 = fmaf(w[3], x0, fmaf(w[4], x1, fmaf(w[5], x2, bias[1])));
    o2 = fmaf(w[6], x0, fmaf(w[7], x1, fmaf(w[8], x2, bias[2])));
}

__device__ __forceinline__ void load_wff(float4* s_wff, const float* w1, const float* b1,
                                         const float* w2) {
    for (int h = threadIdx.x; h < HIDN; h += 256) {
        s_wff[2*h]   = make_float4(w1[h*3], w1[h*3+1], w1[h*3+2], b1[h]);
        s_wff[2*h+1] = make_float4(w2[h], w2[HIDN + h], w2[2*HIDN + h], 0.f);
    }
    __syncthreads();
}

// pos_enc row s: first 3 sin columns, invf[e] = 10000^(-2e/256)
__device__ __forceinline__ void pos3(int s, float& p0, float& p1, float& p2) {
    const float f1 = (float)0.93057204868496882;  // 10000^(-2/256)
    const float f2 = (float)0.86596432336006538;  // 10000^(-4/256)
    float a0 = (float)s;
    p0 = sinf(a0);
    p1 = sinf(a0 * f1);
    p2 = sinf(a0 * f2);
}

// One CTA = one batch. 7 CTAs/SM -> single wave for grid 1024.
__global__ void __launch_bounds__(256, 7)
fused_transformer_kernel(Params P) {
    // 16 KB union, time-multiplexed:
    //   attn phases: kv pairs (float4 k, float4 v per key) + partial region
    //   ffn phases:  packed weights (2 float4 per h)
    __shared__ __align__(16) float4 s_U[1024];
    __shared__ float s_bufA[SIN * 3];
    __shared__ float s_bufR[SIN * 3];
    __shared__ float s_x2[SIN * 3];
    __shared__ float s_enc[SIN * 3];
    __shared__ float s_red[32];

    const int b    = blockIdx.x;
    const int t    = threadIdx.x;
    const int r128 = t & 127, half2 = t >> 7;   // 2-way split id
    const int r64  = t & 63,  q4    = t >> 6;   // 4-way split id

    float pe0, pe1, pe2;
    pos3(t, pe0, pe1, pe2);

    // ================= ENCODER =================
    // E1: pX = X + pos_enc
    {
        const float* xr = P.X + ((size_t)b * SIN + t) * 3;
        s_bufA[t*3+0] = xr[0] + pe0;
        s_bufA[t*3+1] = xr[1] + pe1;
        s_bufA[t*3+2] = xr[2] + pe2;
    }
    __syncthreads();

    // E2: K/V for key t -> s_U[0..512)
    {
        float x0 = s_bufA[t*3], x1 = s_bufA[t*3+1], x2v = s_bufA[t*3+2];
        float k0,k1,k2, v0,v1,v2;
        proj3(P.enc_in_w + 9,  P.enc_in_b + 3, x0, x1, x2v, k0, k1, k2);
        proj3(P.enc_in_w + 18, P.enc_in_b + 6, x0, x1, x2v, v0, v1, v2);
        s_U[2*t]   = make_float4(k0, k1, k2, 0.f);
        s_U[2*t+1] = make_float4(v0, v1, v2, 0.f);
    }
    __syncthreads();

    // E3: self-attention. Each thread: 2 queries {r128, r128+128} x 128 keys.
    {
        int rowA = r128, rowB = r128 + 128;
        float qA0,qA1,qA2, qB0,qB1,qB2;
        proj3(P.enc_in_w, P.enc_in_b, s_bufA[rowA*3], s_bufA[rowA*3+1], s_bufA[rowA*3+2], qA0,qA1,qA2);
        proj3(P.enc_in_w, P.enc_in_b, s_bufA[rowB*3], s_bufA[rowB*3+1], s_bufA[rowB*3+2], qB0,qB1,qB2);
        qA0*=C_SCALE; qA1*=C_SCALE; qA2*=C_SCALE;
        qB0*=C_SCALE; qB1*=C_SCALE; qB2*=C_SCALE;
        float lA=0.f,aA0=0.f,aA1=0.f,aA2=0.f;
        float lB=0.f,aB0=0.f,aB1=0.f,aB2=0.f;
        int j0 = half2 * 128;
        #pragma unroll 4
        for (int j = j0; j < j0 + 128; ++j) {
            float4 k = s_U[2*j];
            float4 v = s_U[2*j+1];
            float sA = fmaf(qA2, k.z, fmaf(qA1, k.y, qA0 * k.x));
            float sB = fmaf(qB2, k.z, fmaf(qB1, k.y, qB0 * k.x));
            float pA = ex2f(sA), pB = ex2f(sB);
            lA += pA; aA0 = fmaf(pA, v.x, aA0); aA1 = fmaf(pA, v.y, aA1); aA2 = fmaf(pA, v.z, aA2);
            lB += pB; aB0 = fmaf(pB, v.x, aB0); aB1 = fmaf(pB, v.y, aB1); aB2 = fmaf(pB, v.z, aB2);
        }
        s_U[512 + rowA*2 + half2] = make_float4(lA, aA0, aA1, aA2);
        s_U[512 + rowB*2 + half2] = make_float4(lB, aB0, aB1, aB2);
    }
    __syncthreads();
    // E3b: merge halves, out-proj, residual
    {
        float4 pa = s_U[512 + t*2], pb = s_U[512 + t*2 + 1];
        float inv = rcpf(pa.x + pb.x);
        float r0, r1, r2;
        proj3(P.enc_out_w, P.enc_out_b, (pa.y+pb.y)*inv, (pa.z+pb.z)*inv, (pa.w+pb.w)*inv, r0, r1, r2);
        s_bufR[t*3+0] = r0 + s_bufA[t*3+0];
        s_bufR[t*3+1] = r1 + s_bufA[t*3+1];
        s_bufR[t*3+2] = r2 + s_bufA[t*3+2];
    }
    __syncthreads();
    layer_norm(s_bufR, s_x2, SIN, P.enc_ln1_w, P.enc_ln1_b, s_red);

    // E5: FFN. Each thread: 2 rows {r128, r128+128} x 256 hidden (half).
    load_wff(s_U, P.enc_lin1_w, P.enc_lin1_b, P.enc_lin2_w);
    {
        int rowA = r128, rowB = r128 + 128;
        float xA0=s_x2[rowA*3], xA1=s_x2[rowA*3+1], xA2=s_x2[rowA*3+2];
        float xB0=s_x2[rowB*3], xB1=s_x2[rowB*3+1], xB2=s_x2[rowB*3+2];
        float aA0=0.f,aA1=0.f,aA2=0.f, aB0=0.f,aB1=0.f,aB2=0.f;
        int h0 = half2 * 256;
        #pragma unroll 4
        for (int h = h0; h < h0 + 256; ++h) {
            float4 w1 = s_U[2*h];
            float4 w2 = s_U[2*h+1];
            float tA = fmaxf(fmaf(w1.x, xA0, fmaf(w1.y, xA1, fmaf(w1.z, xA2, w1.w))), 0.f);
            float tB = fmaxf(fmaf(w1.x, xB0, fmaf(w1.y, xB1, fmaf(w1.z, xB2, w1.w))), 0.f);
            aA0 = fmaf(tA, w2.x, aA0); aA1 = fmaf(tA, w2.y, aA1); aA2 = fmaf(tA, w2.z, aA2);
            aB0 = fmaf(tB, w2.x, aB0); aB1 = fmaf(tB, w2.y, aB1); aB2 = fmaf(tB, w2.z, aB2);
        }
        float* dst = half2 ? s_bufR : s_bufA;
        dst[rowA*3+0]=aA0; dst[rowA*3+1]=aA1; dst[rowA*3+2]=aA2;
        dst[rowB*3+0]=aB0; dst[rowB*3+1]=aB1; dst[rowB*3+2]=aB2;
    }
    __syncthreads();
    {
        float eb0 = P.enc_lin2_b[0], eb1 = P.enc_lin2_b[1], eb2 = P.enc_lin2_b[2];
        s_bufR[t*3+0] = s_bufA[t*3+0] + s_bufR[t*3+0] + eb0 + s_x2[t*3+0];
        s_bufR[t*3+1] = s_bufA[t*3+1] + s_bufR[t*3+1] + eb1 + s_x2[t*3+1];
        s_bufR[t*3+2] = s_bufA[t*3+2] + s_bufR[t*3+2] + eb2 + s_x2[t*3+2];
    }
    __syncthreads();
    layer_norm(s_bufR, s_enc, SIN, P.enc_ln2_w, P.enc_ln2_b, s_red);

    // ================= DECODER =================
    // D1: pT + self-attn K/V -> s_U[0..256)
    if (t < SPR) {
        const float* tr = P.T + ((size_t)b * SPR + t) * 3;
        float x0 = tr[0] + pe0, x1 = tr[1] + pe1, x2v = tr[2] + pe2;
        s_bufA[t*3+0] = x0; s_bufA[t*3+1] = x1; s_bufA[t*3+2] = x2v;
        float k0,k1,k2, v0,v1,v2;
        proj3(P.dec_a1_in_w + 9,  P.dec_a1_in_b + 3, x0, x1, x2v, k0, k1, k2);
        proj3(P.dec_a1_in_w + 18, P.dec_a1_in_b + 6, x0, x1, x2v, v0, v1, v2);
        s_U[2*t]   = make_float4(k0, k1, k2, 0.f);
        s_U[2*t+1] = make_float4(v0, v1, v2, 0.f);
    }
    __syncthreads();

    // D2: dec self-attn. 2 queries {r64, r64+64} x 32 keys (quarter q4).
    // mask: reference ADDS tril(ones) -> multiply p by e where j <= row.
    {
        int rowA = r64, rowB = r64 + 64;
        float qA0,qA1,qA2, qB0,qB1,qB2;
        proj3(P.dec_a1_in_w, P.dec_a1_in_b, s_bufA[rowA*3], s_bufA[rowA*3+1], s_bufA[rowA*3+2], qA0,qA1,qA2);
        proj3(P.dec_a1_in_w, P.dec_a1_in_b, s_bufA[rowB*3], s_bufA[rowB*3+1], s_bufA[rowB*3+2], qB0,qB1,qB2);
        qA0*=C_SCALE; qA1*=C_SCALE; qA2*=C_SCALE;
        qB0*=C_SCALE; qB1*=C_SCALE; qB2*=C_SCALE;
        float lA=0.f,aA0=0.f,aA1=0.f,aA2=0.f;
        float lB=0.f,aB0=0.f,aB1=0.f,aB2=0.f;
        int j0 = q4 * 32;
        #pragma unroll 4
        for (int j = j0; j < j0 + 32; ++j) {
            float4 k = s_U[2*j];
            float4 v = s_U[2*j+1];
            float sA = fmaf(qA2, k.z, fmaf(qA1, k.y, qA0 * k.x));
            float sB = fmaf(qB2, k.z, fmaf(qB1, k.y, qB0 * k.x));
            float pA = ex2f(sA) * ((j <= rowA) ? MASK_E : 1.0f);
            float pB = ex2f(sB) * ((j <= rowB) ? MASK_E : 1.0f);
            lA += pA; aA0 = fmaf(pA, v.x, aA0); aA1 = fmaf(pA, v.y, aA1); aA2 = fmaf(pA, v.z, aA2);
            lB += pB; aB0 = fmaf(pB, v.x, aB0); aB1 = fmaf(pB, v.y, aB1); aB2 = fmaf(pB, v.z, aB2);
        }
        s_U[256 + rowA*4 + q4] = make_float4(lA, aA0, aA1, aA2);
        s_U[256 + rowB*4 + q4] = make_float4(lB, aB0, aB1, aB2);
    }
    __syncthreads();
    if (t < SPR) {
        float4 p0 = s_U[256 + t*4], p1 = s_U[256 + t*4 + 1];
        float4 p2 = s_U[256 + t*4 + 2], p3 = s_U[256 + t*4 + 3];
        float inv = rcpf(p0.x + p1.x + p2.x + p3.x);
        float r0, r1, r2;
        proj3(P.dec_a1_out_w, P.dec_a1_out_b,
              (p0.y+p1.y+p2.y+p3.y)*inv, (p0.z+p1.z+p2.z+p3.z)*inv, (p0.w+p1.w+p2.w+p3.w)*inv,
              r0, r1, r2);
        s_bufR[t*3+0] = r0 + s_bufA[t*3+0];
        s_bufR[t*3+1] = r1 + s_bufA[t*3+1];
        s_bufR[t*3+2] = r2 + s_bufA[t*3+2];
    }
    __syncthreads();
    layer_norm(s_bufR, s_x2, SPR, P.dec_ln1_w, P.dec_ln1_b, s_red);

    // D3: cross K/V from enc_out (key t) -> s_U[0..512)
    {
        float x0 = s_enc[t*3], x1 = s_enc[t*3+1], x2v = s_enc[t*3+2];
        float k0,k1,k2, v0,v1,v2;
        proj3(P.dec_a2_in_w + 9,  P.dec_a2_in_b + 3, x0, x1, x2v, k0, k1, k2);
        proj3(P.dec_a2_in_w + 18, P.dec_a2_in_b + 6, x0, x1, x2v, v0, v1, v2);
        s_U[2*t]   = make_float4(k0, k1, k2, 0.f);
        s_U[2*t+1] = make_float4(v0, v1, v2, 0.f);
    }
    __syncthreads();

    // D4: cross-attn. 2 queries {r64, r64+64} x 64 keys (quarter q4).
    {
        int rowA = r64, rowB = r64 + 64;
        float qA0,qA1,qA2, qB0,qB1,qB2;
        proj3(P.dec_a2_in_w, P.dec_a2_in_b, s_x2[rowA*3], s_x2[rowA*3+1], s_x2[rowA*3+2], qA0,qA1,qA2);
        proj3(P.dec_a2_in_w, P.dec_a2_in_b, s_x2[rowB*3], s_x2[rowB*3+1], s_x2[rowB*3+2], qB0,qB1,qB2);
        qA0*=C_SCALE; qA1*=C_SCALE; qA2*=C_SCALE;
        qB0*=C_SCALE; qB1*=C_SCALE; qB2*=C_SCALE;
        float lA=0.f,aA0=0.f,aA1=0.f,aA2=0.f;
        float lB=0.f,aB0=0.f,aB1=0.f,aB2=0.f;
        int j0 = q4 * 64;
        #pragma unroll 4
        for (int j = j0; j < j0 + 64; ++j) {
            float4 k = s_U[2*j];
            float4 v = s_U[2*j+1];
            float sA = fmaf(qA2, k.z, fmaf(qA1, k.y, qA0 * k.x));
            float sB = fmaf(qB2, k.z, fmaf(qB1, k.y, qB0 * k.x));
            float pA = ex2f(sA), pB = ex2f(sB);
            lA += pA; aA0 = fmaf(pA, v.x, aA0); aA1 = fmaf(pA, v.y, aA1); aA2 = fmaf(pA, v.z, aA2);
            lB += pB; aB0 = fmaf(pB, v.x, aB0); aB1 = fmaf(pB, v.y, aB1); aB2 = fmaf(pB, v.z, aB2);
        }
        s_U[512 + rowA*4 + q4] = make_float4(lA, aA0, aA1, aA2);
        s_U[512 + rowB*4 + q4] = make_float4(lB, aB0, aB1, aB2);
    }
    __syncthreads();
    if (t < SPR) {
        float4 p0 = s_U[512 + t*4], p1 = s_U[512 + t*4 + 1];
        float4 p2 = s_U[512 + t*4 + 2], p3 = s_U[512 + t*4 + 3];
        float inv = rcpf(p0.x + p1.x + p2.x + p3.x);
        float r0, r1, r2;
        proj3(P.dec_a2_out_w, P.dec_a2_out_b,
              (p0.y+p1.y+p2.y+p3.y)*inv, (p0.z+p1.z+p2.z+p3.z)*inv, (p0.w+p1.w+p2.w+p3.w)*inv,
              r0, r1, r2);
        s_bufR[t*3+0] = r0 + s_x2[t*3+0];
        s_bufR[t*3+1] = r1 + s_x2[t*3+1];
        s_bufR[t*3+2] = r2 + s_x2[t*3+2];
    }
    __syncthreads();
    layer_norm(s_bufR, s_x2, SPR, P.dec_ln1_w, P.dec_ln1_b, s_red);  // x3

    // D5: dec FFN. 2 rows {r64, r64+64} x 128 hidden (quarter q4).
    load_wff(s_U, P.dec_lin1_w, P.dec_lin1_b, P.dec_lin2_w);
    {
        int rowA = r64, rowB = r64 + 64;
        float xA0=s_x2[rowA*3], xA1=s_x2[rowA*3+1], xA2=s_x2[rowA*3+2];
        float xB0=s_x2[rowB*3], xB1=s_x2[rowB*3+1], xB2=s_x2[rowB*3+2];
        float aA0=0.f,aA1=0.f,aA2=0.f, aB0=0.f,aB1=0.f,aB2=0.f;
        int h0 = q4 * 128;
        #pragma unroll 4
        for (int h = h0; h < h0 + 128; ++h) {
            float4 w1 = s_U[2*h];
            float4 w2 = s_U[2*h+1];
            float tA = fmaxf(fmaf(w1.x, xA0, fmaf(w1.y, xA1, fmaf(w1.z, xA2, w1.w))), 0.f);
            float tB = fmaxf(fmaf(w1.x, xB0, fmaf(w1.y, xB1, fmaf(w1.z, xB2, w1.w))), 0.f);
            aA0 = fmaf(tA, w2.x, aA0); aA1 = fmaf(tA, w2.y, aA1); aA2 = fmaf(tA, w2.z, aA2);
            aB0 = fmaf(tB, w2.x, aB0); aB1 = fmaf(tB, w2.y, aB1); aB2 = fmaf(tB, w2.z, aB2);
        }
        float* dst = (q4 < 2) ? s_bufA : s_enc;
        int off = (q4 & 1) * 384;
        dst[off + rowA*3+0]=aA0; dst[off + rowA*3+1]=aA1; dst[off + rowA*3+2]=aA2;
        dst[off + rowB*3+0]=aB0; dst[off + rowB*3+1]=aB1; dst[off + rowB*3+2]=aB2;
    }
    __syncthreads();
    if (t < SPR) {
        float db0 = P.dec_lin2_b[0], db1 = P.dec_lin2_b[1], db2 = P.dec_lin2_b[2];
        s_bufR[t*3+0] = s_bufA[t*3+0] + s_bufA[384+t*3+0] + s_enc[t*3+0] + s_enc[384+t*3+0] + db0 + s_x2[t*3+0];
        s_bufR[t*3+1] = s_bufA[t*3+1] + s_bufA[384+t*3+1] + s_enc[t*3+1] + s_enc[384+t*3+1] + db1 + s_x2[t*3+1];
        s_bufR[t*3+2] = s_bufA[t*3+2] + s_bufA[384+t*3+2] + s_enc[t*3+2] + s_enc[384+t*3+2] + db2 + s_x2[t*3+2];
    }
    __syncthreads();
    layer_norm(s_bufR, s_bufA, SPR, P.dec_ln3_w, P.dec_ln3_b, s_red);

    if (t < SPR) {
        float* o = P.out + ((size_t)b * SPR + t) * 3;
        o[0] = s_bufA[t*3+0];
        o[1] = s_bufA[t*3+1];
        o[2] = s_bufA[t*3+2];
    }
}

extern "C" void kernel_launch(void* const* d_in, const int* in_sizes, int n_in,
                              void* d_out, int out_size) {
    (void)in_sizes; (void)n_in; (void)out_size;
    Params P;
    P.X            = (const float*)d_in[0];
    P.T            = (const float*)d_in[1];
    P.enc_in_w     = (const float*)d_in[2];
    P.enc_in_b     = (const float*)d_in[3];
    P.enc_out_w    = (const float*)d_in[4];
    P.enc_out_b    = (const float*)d_in[5];
    P.enc_ln1_w    = (const float*)d_in[6];
    P.enc_ln1_b    = (const float*)d_in[7];
    P.enc_lin1_w   = (const float*)d_in[8];
    P.enc_lin1_b   = (const float*)d_in[9];
    P.enc_lin2_w   = (const float*)d_in[10];
    P.enc_lin2_b   = (const float*)d_in[11];
    P.enc_ln2_w    = (const float*)d_in[12];
    P.enc_ln2_b    = (const float*)d_in[13];
    P.dec_a1_in_w  = (const float*)d_in[14];
    P.dec_a1_in_b  = (const float*)d_in[15];
    P.dec_a1_out_w = (const float*)d_in[16];
    P.dec_a1_out_b = (const float*)d_in[17];
    P.dec_ln1_w    = (const float*)d_in[18];
    P.dec_ln1_b    = (const float*)d_in[19];
    P.dec_a2_in_w  = (const float*)d_in[20];
    P.dec_a2_in_b  = (const float*)d_in[21];
    P.dec_a2_out_w = (const float*)d_in[22];
    P.dec_a2_out_b = (const float*)d_in[23];
    P.dec_lin1_w   = (const float*)d_in[24];
    P.dec_lin1_b   = (const float*)d_in[25];
    P.dec_lin2_w   = (const float*)d_in[26];
    P.dec_lin2_b   = (const float*)d_in[27];
    P.dec_ln3_w    = (const float*)d_in[28];
    P.dec_ln3_b    = (const float*)d_in[29];
    P.out          = (float*)d_out;

    fused_transformer_kernel<<<NB, 256>>>(P);
}

// round 4
// speedup vs baseline: 1.8911x; 1.0145x over previous
#include <cuda_runtime.h>
#include <math.h>

#define NB    1024
#define SIN   256
#define SPR   128
#define HIDN  512

// 1/sqrt(3) * log2(e): fold scores into exp2 domain
#define C_SCALE 0.83294064f
// exp(1): additive mask of +1.0 becomes multiplicative e after exp
#define MASK_E  2.7182818f

struct Params {
    const float* X;           const float* T;
    const float* enc_in_w;    const float* enc_in_b;
    const float* enc_out_w;   const float* enc_out_b;
    const float* enc_ln1_w;   const float* enc_ln1_b;
    const float* enc_lin1_w;  const float* enc_lin1_b;
    const float* enc_lin2_w;  const float* enc_lin2_b;
    const float* enc_ln2_w;   const float* enc_ln2_b;
    const float* dec_a1_in_w; const float* dec_a1_in_b;
    const float* dec_a1_out_w;const float* dec_a1_out_b;
    const float* dec_ln1_w;   const float* dec_ln1_b;
    const float* dec_a2_in_w; const float* dec_a2_in_b;
    const float* dec_a2_out_w;const float* dec_a2_out_b;
    const float* dec_lin1_w;  const float* dec_lin1_b;
    const float* dec_lin2_w;  const float* dec_lin2_b;
    const float* dec_ln3_w;   const float* dec_ln3_b;
    float* out;
};

__device__ __forceinline__ float ex2f(float x) {
    float y; asm("ex2.approx.ftz.f32 %0, %1;" : "=f"(y) : "f"(x)); return y;
}
__device__ __forceinline__ float rcpf(float x) {
    float y; asm("rcp.approx.ftz.f32 %0, %1;" : "=f"(y) : "f"(x)); return y;
}

__device__ __forceinline__ float block_sum(float v, float* red) {
    #pragma unroll
    for (int o = 16; o; o >>= 1) v += __shfl_xor_sync(0xffffffffu, v, o);
    int w = threadIdx.x >> 5;
    if ((threadIdx.x & 31) == 0) red[w] = v;
    __syncthreads();
    if (threadIdx.x < 32) {
        float x = (threadIdx.x < 8) ? red[threadIdx.x] : 0.f;
        #pragma unroll
        for (int o = 4; o; o >>= 1) x += __shfl_xor_sync(0xffffffffu, x, o);
        if (threadIdx.x == 0) red[0] = x;
    }
    __syncthreads();
    float r = red[0];
    __syncthreads();
    return r;
}

// LN over all nrows*3 elems jointly (axes (-2,-1)), per-(s,e) affine.
__device__ __forceinline__ void layer_norm(const float* src, float* dst, int nrows,
                                           const float* w, const float* bb, float* red) {
    int t = threadIdx.x;
    float x0 = 0.f, x1 = 0.f, x2 = 0.f;
    if (t < nrows) { x0 = src[t*3]; x1 = src[t*3+1]; x2 = src[t*3+2]; }
    float n = (float)(nrows * 3);
    float mean = block_sum((t < nrows) ? (x0 + x1 + x2) : 0.f, red) / n;
    float d0 = x0 - mean, d1 = x1 - mean, d2 = x2 - mean;
    float var = block_sum((t < nrows) ? (d0*d0 + d1*d1 + d2*d2) : 0.f, red) / n;
    float rs = rsqrtf(var + 1e-5f);
    if (t < nrows) {
        dst[t*3+0] = d0 * rs * w[t*3+0] + bb[t*3+0];
        dst[t*3+1] = d1 * rs * w[t*3+1] + bb[t*3+1];
        dst[t*3+2] = d2 * rs * w[t*3+2] + bb[t*3+2];
    }
    __syncthreads();
}

__device__ __forceinline__ void proj3(const float* w, const float* bias,
                                      float x0, float x1, float x2,
                                      float& o0, float& o1, float& o2) {
    o0 = fmaf(w[0], x0, fmaf(w[1], x1, fmaf(w[2], x2, bias[0])));
    o1 = fmaf(w[3], x0, fmaf(w[4], x1, fmaf(w[5], x2, bias[1])));
    o2 = fmaf(w[6], x0, fmaf(w[7], x1, fmaf(w[8], x2, bias[2])));
}

// Transposed 3x3 (no bias): o_i = sum_m w[m*3+i] * x_m
__device__ __forceinline__ void proj3T(const float* w,
                                       float x0, float x1, float x2,
                                       float& o0, float& o1, float& o2) {
    o0 = fmaf(w[0], x0, fmaf(w[3], x1, w[6] * x2));
    o1 = fmaf(w[1], x0, fmaf(w[4], x1, w[7] * x2));
    o2 = fmaf(w[2], x0, fmaf(w[5], x1, w[8] * x2));
}

// q' = (Wk^T (Wq x + bq)) * C_SCALE; bk dropped (cancels in softmax)
__device__ __forceinline__ void make_q(const float* in_w, const float* in_b,
                                       float x0, float x1, float x2,
                                       float& q0, float& q1, float& q2) {
    float t0, t1, t2;
    proj3(in_w, in_b, x0, x1, x2, t0, t1, t2);
    proj3T(in_w + 9, t0, t1, t2, q0, q1, q2);
    q0 *= C_SCALE; q1 *= C_SCALE; q2 *= C_SCALE;
}

__device__ __forceinline__ void load_wff(float4* s_wff, const float* w1, const float* b1,
                                         const float* w2) {
    for (int h = threadIdx.x; h < HIDN; h += 256) {
        s_wff[2*h]   = make_float4(w1[h*3], w1[h*3+1], w1[h*3+2], b1[h]);
        s_wff[2*h+1] = make_float4(w2[h], w2[HIDN + h], w2[2*HIDN + h], 0.f);
    }
    __syncthreads();
}

// pos_enc row s: first 3 sin columns, invf[e] = 10000^(-2e/256)
__device__ __forceinline__ void pos3(int s, float& p0, float& p1, float& p2) {
    const float f1 = (float)0.93057204868496882;  // 10000^(-2/256)
    const float f2 = (float)0.86596432336006538;  // 10000^(-4/256)
    float a0 = (float)s;
    p0 = sinf(a0);
    p1 = sinf(a0 * f1);
    p2 = sinf(a0 * f2);
}

// One CTA = one batch. 7 CTAs/SM -> single wave for grid 1024.
__global__ void __launch_bounds__(256, 7)
fused_transformer_kernel(Params P) {
    // 16 KB union, time-multiplexed:
    //   attn phases: raw key-side inputs (1 float4/key) + partial regions
    //   ffn phases:  packed weights (2 float4 per h)
    __shared__ __align__(16) float4 s_U[1024];
    __shared__ float s_bufA[SIN * 3];
    __shared__ float s_bufR[SIN * 3];
    __shared__ float s_x2[SIN * 3];
    __shared__ float s_enc[SIN * 3];
    __shared__ float s_red[32];

    const int b    = blockIdx.x;
    const int t    = threadIdx.x;
    const int r128 = t & 127, half2 = t >> 7;   // 2-way split id
    const int r64  = t & 63,  q4    = t >> 6;   // 4-way split id

    float pe0, pe1, pe2;
    pos3(t, pe0, pe1, pe2);

    // ================= ENCODER =================
    // E1: pX = X + pos_enc -> s_U[0..256) as float4 (raw key-side input)
    {
        const float* xr = P.X + ((size_t)b * SIN + t) * 3;
        s_U[t] = make_float4(xr[0] + pe0, xr[1] + pe1, xr[2] + pe2, 0.f);
    }
    __syncthreads();

    // E2: self-attention on raw x. 2 queries {r128, r128+128} x 128 keys.
    {
        int rowA = r128, rowB = r128 + 128;
        float4 xA = s_U[rowA], xB = s_U[rowB];
        float qA0,qA1,qA2, qB0,qB1,qB2;
        make_q(P.enc_in_w, P.enc_in_b, xA.x, xA.y, xA.z, qA0, qA1, qA2);
        make_q(P.enc_in_w, P.enc_in_b, xB.x, xB.y, xB.z, qB0, qB1, qB2);
        float lA=0.f,aA0=0.f,aA1=0.f,aA2=0.f;
        float lB=0.f,aB0=0.f,aB1=0.f,aB2=0.f;
        int j0 = half2 * 128;
        #pragma unroll 4
        for (int j = j0; j < j0 + 128; ++j) {
            float4 x = s_U[j];
            float sA = fmaf(qA2, x.z, fmaf(qA1, x.y, qA0 * x.x));
            float sB = fmaf(qB2, x.z, fmaf(qB1, x.y, qB0 * x.x));
            float pA = ex2f(sA), pB = ex2f(sB);
            lA += pA; aA0 = fmaf(pA, x.x, aA0); aA1 = fmaf(pA, x.y, aA1); aA2 = fmaf(pA, x.z, aA2);
            lB += pB; aB0 = fmaf(pB, x.x, aB0); aB1 = fmaf(pB, x.y, aB1); aB2 = fmaf(pB, x.z, aB2);
        }
        s_U[256 + rowA*2 + half2] = make_float4(lA, aA0, aA1, aA2);
        s_U[256 + rowB*2 + half2] = make_float4(lB, aB0, aB1, aB2);
    }
    __syncthreads();
    // E2b: merge halves, apply Wv then out-proj, residual
    {
        float4 pa = s_U[256 + t*2], pb = s_U[256 + t*2 + 1];
        float4 xt = s_U[t];
        float inv = rcpf(pa.x + pb.x);
        float v0, v1, v2;
        proj3(P.enc_in_w + 18, P.enc_in_b + 6,
              (pa.y+pb.y)*inv, (pa.z+pb.z)*inv, (pa.w+pb.w)*inv, v0, v1, v2);
        float r0, r1, r2;
        proj3(P.enc_out_w, P.enc_out_b, v0, v1, v2, r0, r1, r2);
        s_bufR[t*3+0] = r0 + xt.x;
        s_bufR[t*3+1] = r1 + xt.y;
        s_bufR[t*3+2] = r2 + xt.z;
    }
    __syncthreads();
    layer_norm(s_bufR, s_x2, SIN, P.enc_ln1_w, P.enc_ln1_b, s_red);

    // E3: FFN. 2 rows {r128, r128+128} x 256 hidden (half).
    load_wff(s_U, P.enc_lin1_w, P.enc_lin1_b, P.enc_lin2_w);
    {
        int rowA = r128, rowB = r128 + 128;
        float xA0=s_x2[rowA*3], xA1=s_x2[rowA*3+1], xA2=s_x2[rowA*3+2];
        float xB0=s_x2[rowB*3], xB1=s_x2[rowB*3+1], xB2=s_x2[rowB*3+2];
        float aA0=0.f,aA1=0.f,aA2=0.f, aB0=0.f,aB1=0.f,aB2=0.f;
        int h0 = half2 * 256;
        #pragma unroll 4
        for (int h = h0; h < h0 + 256; ++h) {
            float4 w1 = s_U[2*h];
            float4 w2 = s_U[2*h+1];
            float tA = fmaxf(fmaf(w1.x, xA0, fmaf(w1.y, xA1, fmaf(w1.z, xA2, w1.w))), 0.f);
            float tB = fmaxf(fmaf(w1.x, xB0, fmaf(w1.y, xB1, fmaf(w1.z, xB2, w1.w))), 0.f);
            aA0 = fmaf(tA, w2.x, aA0); aA1 = fmaf(tA, w2.y, aA1); aA2 = fmaf(tA, w2.z, aA2);
            aB0 = fmaf(tB, w2.x, aB0); aB1 = fmaf(tB, w2.y, aB1); aB2 = fmaf(tB, w2.z, aB2);
        }
        float* dst = half2 ? s_bufR : s_bufA;
        dst[rowA*3+0]=aA0; dst[rowA*3+1]=aA1; dst[rowA*3+2]=aA2;
        dst[rowB*3+0]=aB0; dst[rowB*3+1]=aB1; dst[rowB*3+2]=aB2;
    }
    __syncthreads();
    {
        float eb0 = P.enc_lin2_b[0], eb1 = P.enc_lin2_b[1], eb2 = P.enc_lin2_b[2];
        s_bufR[t*3+0] = s_bufA[t*3+0] + s_bufR[t*3+0] + eb0 + s_x2[t*3+0];
        s_bufR[t*3+1] = s_bufA[t*3+1] + s_bufR[t*3+1] + eb1 + s_x2[t*3+1];
        s_bufR[t*3+2] = s_bufA[t*3+2] + s_bufR[t*3+2] + eb2 + s_x2[t*3+2];
    }
    __syncthreads();
    layer_norm(s_bufR, s_enc, SIN, P.enc_ln2_w, P.enc_ln2_b, s_red);

    // ================= DECODER =================
    // D1: pT -> s_U[0..128) as float4 (raw key-side input)
    if (t < SPR) {
        const float* tr = P.T + ((size_t)b * SPR + t) * 3;
        s_U[t] = make_float4(tr[0] + pe0, tr[1] + pe1, tr[2] + pe2, 0.f);
    }
    __syncthreads();

    // D2: dec self-attn. 2 queries {r64, r64+64} x 32 keys (quarter q4).
    // mask: reference ADDS tril(ones) -> multiply p by e where j <= row.
    {
        int rowA = r64, rowB = r64 + 64;
        float4 xA = s_U[rowA], xB = s_U[rowB];
        float qA0,qA1,qA2, qB0,qB1,qB2;
        make_q(P.dec_a1_in_w, P.dec_a1_in_b, xA.x, xA.y, xA.z, qA0, qA1, qA2);
        make_q(P.dec_a1_in_w, P.dec_a1_in_b, xB.x, xB.y, xB.z, qB0, qB1, qB2);
        float lA=0.f,aA0=0.f,aA1=0.f,aA2=0.f;
        float lB=0.f,aB0=0.f,aB1=0.f,aB2=0.f;
        int j0 = q4 * 32;
        #pragma unroll 4
        for (int j = j0; j < j0 + 32; ++j) {
            float4 x = s_U[j];
            float sA = fmaf(qA2, x.z, fmaf(qA1, x.y, qA0 * x.x));
            float sB = fmaf(qB2, x.z, fmaf(qB1, x.y, qB0 * x.x));
            float pA = ex2f(sA) * ((j <= rowA) ? MASK_E : 1.0f);
            float pB = ex2f(sB) * ((j <= rowB) ? MASK_E : 1.0f);
            lA += pA; aA0 = fmaf(pA, x.x, aA0); aA1 = fmaf(pA, x.y, aA1); aA2 = fmaf(pA, x.z, aA2);
            lB += pB; aB0 = fmaf(pB, x.x, aB0); aB1 = fmaf(pB, x.y, aB1); aB2 = fmaf(pB, x.z, aB2);
        }
        s_U[128 + rowA*4 + q4] = make_float4(lA, aA0, aA1, aA2);
        s_U[128 + rowB*4 + q4] = make_float4(lB, aB0, aB1, aB2);
    }
    __syncthreads();
    if (t < SPR) {
        float4 p0 = s_U[128 + t*4], p1 = s_U[128 + t*4 + 1];
        float4 p2 = s_U[128 + t*4 + 2], p3 = s_U[128 + t*4 + 3];
        float4 xt = s_U[t];
        float inv = rcpf(p0.x + p1.x + p2.x + p3.x);
        float v0, v1, v2;
        proj3(P.dec_a1_in_w + 18, P.dec_a1_in_b + 6,
              (p0.y+p1.y+p2.y+p3.y)*inv, (p0.z+p1.z+p2.z+p3.z)*inv, (p0.w+p1.w+p2.w+p3.w)*inv,
              v0, v1, v2);
        float r0, r1, r2;
        proj3(P.dec_a1_out_w, P.dec_a1_out_b, v0, v1, v2, r0, r1, r2);
        s_bufR[t*3+0] = r0 + xt.x;
        s_bufR[t*3+1] = r1 + xt.y;
        s_bufR[t*3+2] = r2 + xt.z;
    }
    __syncthreads();
    layer_norm(s_bufR, s_x2, SPR, P.dec_ln1_w, P.dec_ln1_b, s_red);

    // D3: cross keys = raw enc_out rows -> s_U[0..256)
    s_U[t] = make_float4(s_enc[t*3], s_enc[t*3+1], s_enc[t*3+2], 0.f);
    __syncthreads();

    // D4: cross-attn. 2 queries {r64, r64+64} x 64 keys (quarter q4).
    {
        int rowA = r64, rowB = r64 + 64;
        float qA0,qA1,qA2, qB0,qB1,qB2;
        make_q(P.dec_a2_in_w, P.dec_a2_in_b, s_x2[rowA*3], s_x2[rowA*3+1], s_x2[rowA*3+2], qA0,qA1,qA2);
        make_q(P.dec_a2_in_w, P.dec_a2_in_b, s_x2[rowB*3], s_x2[rowB*3+1], s_x2[rowB*3+2], qB0,qB1,qB2);
        float lA=0.f,aA0=0.f,aA1=0.f,aA2=0.f;
        float lB=0.f,aB0=0.f,aB1=0.f,aB2=0.f;
        int j0 = q4 * 64;
        #pragma unroll 4
        for (int j = j0; j < j0 + 64; ++j) {
            float4 x = s_U[j];
            float sA = fmaf(qA2, x.z, fmaf(qA1, x.y, qA0 * x.x));
            float sB = fmaf(qB2, x.z, fmaf(qB1, x.y, qB0 * x.x));
            float pA = ex2f(sA), pB = ex2f(sB);
            lA += pA; aA0 = fmaf(pA, x.x, aA0); aA1 = fmaf(pA, x.y, aA1); aA2 = fmaf(pA, x.z, aA2);
            lB += pB; aB0 = fmaf(pB, x.x, aB0); aB1 = fmaf(pB, x.y, aB1); aB2 = fmaf(pB, x.z, aB2);
        }
        s_U[256 + rowA*4 + q4] = make_float4(lA, aA0, aA1, aA2);
        s_U[256 + rowB*4 + q4] = make_float4(lB, aB0, aB1, aB2);
    }
    __syncthreads();
    if (t < SPR) {
        float4 p0 = s_U[256 + t*4], p1 = s_U[256 + t*4 + 1];
        float4 p2 = s_U[256 + t*4 + 2], p3 = s_U[256 + t*4 + 3];
        float inv = rcpf(p0.x + p1.x + p2.x + p3.x);
        float v0, v1, v2;
        proj3(P.dec_a2_in_w + 18, P.dec_a2_in_b + 6,
              (p0.y+p1.y+p2.y+p3.y)*inv, (p0.z+p1.z+p2.z+p3.z)*inv, (p0.w+p1.w+p2.w+p3.w)*inv,
              v0, v1, v2);
        float r0, r1, r2;
        proj3(P.dec_a2_out_w, P.dec_a2_out_b, v0, v1, v2, r0, r1, r2);
        s_bufR[t*3+0] = r0 + s_x2[t*3+0];
        s_bufR[t*3+1] = r1 + s_x2[t*3+1];
        s_bufR[t*3+2] = r2 + s_x2[t*3+2];
    }
    __syncthreads();
    layer_norm(s_bufR, s_x2, SPR, P.dec_ln1_w, P.dec_ln1_b, s_red);  // x3

    // D5: dec FFN. 2 rows {r64, r64+64} x 128 hidden (quarter q4).
    load_wff(s_U, P.dec_lin1_w, P.dec_lin1_b, P.dec_lin2_w);
    {
        int rowA = r64, rowB = r64 + 64;
        float xA0=s_x2[rowA*3], xA1=s_x2[rowA*3+1], xA2=s_x2[rowA*3+2];
        float xB0=s_x2[rowB*3], xB1=s_x2[rowB*3+1], xB2=s_x2[rowB*3+2];
        float aA0=0.f,aA1=0.f,aA2=0.f, aB0=0.f,aB1=0.f,aB2=0.f;
        int h0 = q4 * 128;
        #pragma unroll 4
        for (int h = h0; h < h0 + 128; ++h) {
            float4 w1 = s_U[2*h];
            float4 w2 = s_U[2*h+1];
            float tA = fmaxf(fmaf(w1.x, xA0, fmaf(w1.y, xA1, fmaf(w1.z, xA2, w1.w))), 0.f);
            float tB = fmaxf(fmaf(w1.x, xB0, fmaf(w1.y, xB1, fmaf(w1.z, xB2, w1.w))), 0.f);
            aA0 = fmaf(tA, w2.x, aA0); aA1 = fmaf(tA, w2.y, aA1); aA2 = fmaf(tA, w2.z, aA2);
            aB0 = fmaf(tB, w2.x, aB0); aB1 = fmaf(tB, w2.y, aB1); aB2 = fmaf(tB, w2.z, aB2);
        }
        float* dst = (q4 < 2) ? s_bufA : s_enc;
        int off = (q4 & 1) * 384;
        dst[off + rowA*3+0]=aA0; dst[off + rowA*3+1]=aA1; dst[off + rowA*3+2]=aA2;
        dst[off + rowB*3+0]=aB0; dst[off + rowB*3+1]=aB1; dst[off + rowB*3+2]=aB2;
    }
    __syncthreads();
    if (t < SPR) {
        float db0 = P.dec_lin2_b[0], db1 = P.dec_lin2_b[1], db2 = P.dec_lin2_b[2];
        s_bufR[t*3+0] = s_bufA[t*3+0] + s_bufA[384+t*3+0] + s_enc[t*3+0] + s_enc[384+t*3+0] + db0 + s_x2[t*3+0];
        s_bufR[t*3+1] = s_bufA[t*3+1] + s_bufA[384+t*3+1] + s_enc[t*3+1] + s_enc[384+t*3+1] + db1 + s_x2[t*3+1];
        s_bufR[t*3+2] = s_bufA[t*3+2] + s_bufA[384+t*3+2] + s_enc[t*3+2] + s_enc[384+t*3+2] + db2 + s_x2[t*3+2];
    }
    __syncthreads();
    layer_norm(s_bufR, s_bufA, SPR, P.dec_ln3_w, P.dec_ln3_b, s_red);

    if (t < SPR) {
        float* o = P.out + ((size_t)b * SPR + t) * 3;
        o[0] = s_bufA[t*3+0];
        o[1] = s_bufA[t*3+1];
        o[2] = s_bufA[t*3+2];
    }
}

extern "C" void kernel_launch(void* const* d_in, const int* in_sizes, int n_in,
                              void* d_out, int out_size) {
    (void)in_sizes; (void)n_in; (void)out_size;
    Params P;
    P.X            = (const float*)d_in[0];
    P.T            = (const float*)d_in[1];
    P.enc_in_w     = (const float*)d_in[2];
    P.enc_in_b     = (const float*)d_in[3];
    P.enc_out_w    = (const float*)d_in[4];
    P.enc_out_b    = (const float*)d_in[5];
    P.enc_ln1_w    = (const float*)d_in[6];
    P.enc_ln1_b    = (const float*)d_in[7];
    P.enc_lin1_w   = (const float*)d_in[8];
    P.enc_lin1_b   = (const float*)d_in[9];
    P.enc_lin2_w   = (const float*)d_in[10];
    P.enc_lin2_b   = (const float*)d_in[11];
    P.enc_ln2_w    = (const float*)d_in[12];
    P.enc_ln2_b    = (const float*)d_in[13];
    P.dec_a1_in_w  = (const float*)d_in[14];
    P.dec_a1_in_b  = (const float*)d_in[15];
    P.dec_a1_out_w = (const float*)d_in[16];
    P.dec_a1_out_b = (const float*)d_in[17];
    P.dec_ln1_w    = (const float*)d_in[18];
    P.dec_ln1_b    = (const float*)d_in[19];
    P.dec_a2_in_w  = (const float*)d_in[20];
    P.dec_a2_in_b  = (const float*)d_in[21];
    P.dec_a2_out_w = (const float*)d_in[22];
    P.dec_a2_out_b = (const float*)d_in[23];
    P.dec_lin1_w   = (const float*)d_in[24];
    P.dec_lin1_b   = (const float*)d_in[25];
    P.dec_lin2_w   = (const float*)d_in[26];
    P.dec_lin2_b   = (const float*)d_in[27];
    P.dec_ln3_w    = (const float*)d_in[28];
    P.dec_ln3_b    = (const float*)d_in[29];
    P.out          = (float*)d_out;

    fused_transformer_kernel<<<NB, 256>>>(P);
}

// round 5
// speedup vs baseline: 1.9306x; 1.0209x over previous
#include <cuda_runtime.h>
#include <math.h>

#define NB    1024
#define SIN   256
#define SPR   128
#define HIDN  512

// 1/sqrt(3) * log2(e): fold scores into exp2 domain
#define C_SCALE 0.83294064f
// exp(1): additive mask of +1.0 becomes multiplicative e after exp
#define MASK_E  2.7182818f

struct Params {
    const float* X;           const float* T;
    const float* enc_in_w;    const float* enc_in_b;
    const float* enc_out_w;   const float* enc_out_b;
    const float* enc_ln1_w;   const float* enc_ln1_b;
    const float* enc_lin1_w;  const float* enc_lin1_b;
    const float* enc_lin2_w;  const float* enc_lin2_b;
    const float* enc_ln2_w;   const float* enc_ln2_b;
    const float* dec_a1_in_w; const float* dec_a1_in_b;
    const float* dec_a1_out_w;const float* dec_a1_out_b;
    const float* dec_ln1_w;   const float* dec_ln1_b;
    const float* dec_a2_in_w; const float* dec_a2_in_b;
    const float* dec_a2_out_w;const float* dec_a2_out_b;
    const float* dec_lin1_w;  const float* dec_lin1_b;
    const float* dec_lin2_w;  const float* dec_lin2_b;
    const float* dec_ln3_w;   const float* dec_ln3_b;
    float* out;
};

__device__ __forceinline__ float ex2f(float x) {
    float y; asm("ex2.approx.ftz.f32 %0, %1;" : "=f"(y) : "f"(x)); return y;
}
__device__ __forceinline__ float rcpf(float x) {
    float y; asm("rcp.approx.ftz.f32 %0, %1;" : "=f"(y) : "f"(x)); return y;
}

// Fused two-value block reduction (sum of a and b over 256 threads).
// Only 2 __syncthreads. red must hold >= 18 floats.
__device__ __forceinline__ void block_sum2(float& a, float& b, float* red) {
    #pragma unroll
    for (int o = 16; o; o >>= 1) {
        a += __shfl_xor_sync(0xffffffffu, a, o);
        b += __shfl_xor_sync(0xffffffffu, b, o);
    }
    int w = threadIdx.x >> 5;
    if ((threadIdx.x & 31) == 0) { red[w] = a; red[8 + w] = b; }
    __syncthreads();
    if (threadIdx.x < 16) {
        float x = red[threadIdx.x];
        x += __shfl_xor_sync(0x0000ffffu, x, 4);
        x += __shfl_xor_sync(0x0000ffffu, x, 2);
        x += __shfl_xor_sync(0x0000ffffu, x, 1);
        if ((threadIdx.x & 7) == 0) red[16 + (threadIdx.x >> 3)] = x;
    }
    __syncthreads();
    a = red[16]; b = red[17];
    // safe: red[0..15] rewritten only after next call's own barrier,
    // red[16..17] rewritten only after two barriers.
}

// LN over all nrows*3 elems jointly (axes (-2,-1)), per-(s,e) affine.
// Single fused reduction pass: var = E[x^2] - mean^2.
__device__ __forceinline__ void layer_norm(const float* src, float* dst, int nrows,
                                           float inv_n, const float* w, const float* bb,
                                           float* red) {
    int t = threadIdx.x;
    float x0 = 0.f, x1 = 0.f, x2 = 0.f;
    if (t < nrows) { x0 = src[t*3]; x1 = src[t*3+1]; x2 = src[t*3+2]; }
    float s1 = x0 + x1 + x2;
    float s2 = fmaf(x0, x0, fmaf(x1, x1, x2 * x2));
    block_sum2(s1, s2, red);
    float mean = s1 * inv_n;
    float var  = fmaf(-mean, mean, s2 * inv_n);
    float rs = rsqrtf(var + 1e-5f);
    if (t < nrows) {
        dst[t*3+0] = (x0 - mean) * rs * w[t*3+0] + bb[t*3+0];
        dst[t*3+1] = (x1 - mean) * rs * w[t*3+1] + bb[t*3+1];
        dst[t*3+2] = (x2 - mean) * rs * w[t*3+2] + bb[t*3+2];
    }
    __syncthreads();
}

// Final LN writing directly to global output (no trailing barrier needed).
__device__ __forceinline__ void layer_norm_out(const float* src, float* gout, int nrows,
                                               float inv_n, const float* w, const float* bb,
                                               float* red) {
    int t = threadIdx.x;
    float x0 = 0.f, x1 = 0.f, x2 = 0.f;
    if (t < nrows) { x0 = src[t*3]; x1 = src[t*3+1]; x2 = src[t*3+2]; }
    float s1 = x0 + x1 + x2;
    float s2 = fmaf(x0, x0, fmaf(x1, x1, x2 * x2));
    block_sum2(s1, s2, red);
    float mean = s1 * inv_n;
    float var  = fmaf(-mean, mean, s2 * inv_n);
    float rs = rsqrtf(var + 1e-5f);
    if (t < nrows) {
        gout[t*3+0] = (x0 - mean) * rs * w[t*3+0] + bb[t*3+0];
        gout[t*3+1] = (x1 - mean) * rs * w[t*3+1] + bb[t*3+1];
        gout[t*3+2] = (x2 - mean) * rs * w[t*3+2] + bb[t*3+2];
    }
}

__device__ __forceinline__ void proj3(const float* w, const float* bias,
                                      float x0, float x1, float x2,
                                      float& o0, float& o1, float& o2) {
    o0 = fmaf(w[0], x0, fmaf(w[1], x1, fmaf(w[2], x2, bias[0])));
    o1 = fmaf(w[3], x0, fmaf(w[4], x1, fmaf(w[5], x2, bias[1])));
    o2 = fmaf(w[6], x0, fmaf(w[7], x1, fmaf(w[8], x2, bias[2])));
}

// Transposed 3x3 (no bias): o_i = sum_m w[m*3+i] * x_m
__device__ __forceinline__ void proj3T(const float* w,
                                       float x0, float x1, float x2,
                                       float& o0, float& o1, float& o2) {
    o0 = fmaf(w[0], x0, fmaf(w[3], x1, w[6] * x2));
    o1 = fmaf(w[1], x0, fmaf(w[4], x1, w[7] * x2));
    o2 = fmaf(w[2], x0, fmaf(w[5], x1, w[8] * x2));
}

// q' = (Wk^T (Wq x + bq)) * C_SCALE; bk dropped (cancels in softmax)
__device__ __forceinline__ void make_q(const float* in_w, const float* in_b,
                                       float x0, float x1, float x2,
                                       float& q0, float& q1, float& q2) {
    float t0, t1, t2;
    proj3(in_w, in_b, x0, x1, x2, t0, t1, t2);
    proj3T(in_w + 9, t0, t1, t2, q0, q1, q2);
    q0 *= C_SCALE; q1 *= C_SCALE; q2 *= C_SCALE;
}

__device__ __forceinline__ void load_wff(float4* s_wff, const float* w1, const float* b1,
                                         const float* w2) {
    for (int h = threadIdx.x; h < HIDN; h += 256) {
        s_wff[2*h]   = make_float4(w1[h*3], w1[h*3+1], w1[h*3+2], b1[h]);
        s_wff[2*h+1] = make_float4(w2[h], w2[HIDN + h], w2[2*HIDN + h], 0.f);
    }
    __syncthreads();
}

// pos_enc row s: first 3 sin columns, invf[e] = 10000^(-2e/256)
__device__ __forceinline__ void pos3(int s, float& p0, float& p1, float& p2) {
    const float f1 = (float)0.93057204868496882;  // 10000^(-2/256)
    const float f2 = (float)0.86596432336006538;  // 10000^(-4/256)
    float a0 = (float)s;
    p0 = sinf(a0);
    p1 = sinf(a0 * f1);
    p2 = sinf(a0 * f2);
}

// One CTA = one batch. 8 CTAs/SM (100% occupancy) -> single wave for grid 1024.
__global__ void __launch_bounds__(256, 8)
fused_transformer_kernel(Params P) {
    // 16 KB union, time-multiplexed:
    //   attn phases: raw key-side inputs (1 float4/key) + partial regions
    //   ffn phases:  packed weights (2 float4 per h)
    __shared__ __align__(16) float4 s_U[1024];
    __shared__ float s_x2[SIN * 3];   // LN outputs (x2 / x3)
    __shared__ float s_R[SIN * 3];    // pre-LN residual; FFN partial B
    __shared__ float s_E[SIN * 3];    // encoder output; FFN partial A
    __shared__ float s_red[18];

    const int b    = blockIdx.x;
    const int t    = threadIdx.x;
    const int r128 = t & 127, half2 = t >> 7;   // 2-way split id
    const int r64  = t & 63,  q4    = t >> 6;   // 4-way split id
    const float INV768 = 1.0f / 768.0f;
    const float INV384 = 1.0f / 384.0f;

    float pe0, pe1, pe2;
    pos3(t, pe0, pe1, pe2);

    // ================= ENCODER =================
    // E1: pX = X + pos_enc -> s_U[0..256)
    {
        const float* xr = P.X + ((size_t)b * SIN + t) * 3;
        s_U[t] = make_float4(xr[0] + pe0, xr[1] + pe1, xr[2] + pe2, 0.f);
    }
    __syncthreads();

    // E2: self-attention on raw x. 2 queries {r128, r128+128} x 128 keys.
    {
        int rowA = r128, rowB = r128 + 128;
        float4 xA = s_U[rowA], xB = s_U[rowB];
        float qA0,qA1,qA2, qB0,qB1,qB2;
        make_q(P.enc_in_w, P.enc_in_b, xA.x, xA.y, xA.z, qA0, qA1, qA2);
        make_q(P.enc_in_w, P.enc_in_b, xB.x, xB.y, xB.z, qB0, qB1, qB2);
        float lA=0.f,aA0=0.f,aA1=0.f,aA2=0.f;
        float lB=0.f,aB0=0.f,aB1=0.f,aB2=0.f;
        int j0 = half2 * 128;
        #pragma unroll 4
        for (int j = j0; j < j0 + 128; ++j) {
            float4 x = s_U[j];
            float sA = fmaf(qA2, x.z, fmaf(qA1, x.y, qA0 * x.x));
            float sB = fmaf(qB2, x.z, fmaf(qB1, x.y, qB0 * x.x));
            float pA = ex2f(sA), pB = ex2f(sB);
            lA += pA; aA0 = fmaf(pA, x.x, aA0); aA1 = fmaf(pA, x.y, aA1); aA2 = fmaf(pA, x.z, aA2);
            lB += pB; aB0 = fmaf(pB, x.x, aB0); aB1 = fmaf(pB, x.y, aB1); aB2 = fmaf(pB, x.z, aB2);
        }
        s_U[256 + rowA*2 + half2] = make_float4(lA, aA0, aA1, aA2);
        s_U[256 + rowB*2 + half2] = make_float4(lB, aB0, aB1, aB2);
    }
    __syncthreads();
    // E2b: merge halves, apply Wv then out-proj, residual
    {
        float4 pa = s_U[256 + t*2], pb = s_U[256 + t*2 + 1];
        float4 xt = s_U[t];
        float inv = rcpf(pa.x + pb.x);
        float v0, v1, v2;
        proj3(P.enc_in_w + 18, P.enc_in_b + 6,
              (pa.y+pb.y)*inv, (pa.z+pb.z)*inv, (pa.w+pb.w)*inv, v0, v1, v2);
        float r0, r1, r2;
        proj3(P.enc_out_w, P.enc_out_b, v0, v1, v2, r0, r1, r2);
        s_R[t*3+0] = r0 + xt.x;
        s_R[t*3+1] = r1 + xt.y;
        s_R[t*3+2] = r2 + xt.z;
    }
    __syncthreads();
    layer_norm(s_R, s_x2, SIN, INV768, P.enc_ln1_w, P.enc_ln1_b, s_red);

    // E3: FFN. 2 rows {r128, r128+128} x 256 hidden (half).
    // Partials: half2=0 -> s_E, half2=1 -> s_R (both dead here).
    load_wff(s_U, P.enc_lin1_w, P.enc_lin1_b, P.enc_lin2_w);
    {
        int rowA = r128, rowB = r128 + 128;
        float xA0=s_x2[rowA*3], xA1=s_x2[rowA*3+1], xA2=s_x2[rowA*3+2];
        float xB0=s_x2[rowB*3], xB1=s_x2[rowB*3+1], xB2=s_x2[rowB*3+2];
        float aA0=0.f,aA1=0.f,aA2=0.f, aB0=0.f,aB1=0.f,aB2=0.f;
        int h0 = half2 * 256;
        #pragma unroll 4
        for (int h = h0; h < h0 + 256; ++h) {
            float4 w1 = s_U[2*h];
            float4 w2 = s_U[2*h+1];
            float tA = fmaxf(fmaf(w1.x, xA0, fmaf(w1.y, xA1, fmaf(w1.z, xA2, w1.w))), 0.f);
            float tB = fmaxf(fmaf(w1.x, xB0, fmaf(w1.y, xB1, fmaf(w1.z, xB2, w1.w))), 0.f);
            aA0 = fmaf(tA, w2.x, aA0); aA1 = fmaf(tA, w2.y, aA1); aA2 = fmaf(tA, w2.z, aA2);
            aB0 = fmaf(tB, w2.x, aB0); aB1 = fmaf(tB, w2.y, aB1); aB2 = fmaf(tB, w2.z, aB2);
        }
        float* dst = half2 ? s_R : s_E;
        dst[rowA*3+0]=aA0; dst[rowA*3+1]=aA1; dst[rowA*3+2]=aA2;
        dst[rowB*3+0]=aB0; dst[rowB*3+1]=aB1; dst[rowB*3+2]=aB2;
    }
    __syncthreads();
    {
        float eb0 = P.enc_lin2_b[0], eb1 = P.enc_lin2_b[1], eb2 = P.enc_lin2_b[2];
        s_R[t*3+0] = s_E[t*3+0] + s_R[t*3+0] + eb0 + s_x2[t*3+0];
        s_R[t*3+1] = s_E[t*3+1] + s_R[t*3+1] + eb1 + s_x2[t*3+1];
        s_R[t*3+2] = s_E[t*3+2] + s_R[t*3+2] + eb2 + s_x2[t*3+2];
    }
    __syncthreads();
    layer_norm(s_R, s_E, SIN, INV768, P.enc_ln2_w, P.enc_ln2_b, s_red);

    // ================= DECODER =================
    // D1: pT -> s_U[0..128)
    if (t < SPR) {
        const float* tr = P.T + ((size_t)b * SPR + t) * 3;
        s_U[t] = make_float4(tr[0] + pe0, tr[1] + pe1, tr[2] + pe2, 0.f);
    }
    __syncthreads();

    // D2: dec self-attn. 2 queries {r64, r64+64} x 32 keys (quarter q4).
    // mask: reference ADDS tril(ones) -> multiply p by e where j <= row.
    {
        int rowA = r64, rowB = r64 + 64;
        float4 xA = s_U[rowA], xB = s_U[rowB];
        float qA0,qA1,qA2, qB0,qB1,qB2;
        make_q(P.dec_a1_in_w, P.dec_a1_in_b, xA.x, xA.y, xA.z, qA0, qA1, qA2);
        make_q(P.dec_a1_in_w, P.dec_a1_in_b, xB.x, xB.y, xB.z, qB0, qB1, qB2);
        float lA=0.f,aA0=0.f,aA1=0.f,aA2=0.f;
        float lB=0.f,aB0=0.f,aB1=0.f,aB2=0.f;
        int j0 = q4 * 32;
        #pragma unroll 4
        for (int j = j0; j < j0 + 32; ++j) {
            float4 x = s_U[j];
            float sA = fmaf(qA2, x.z, fmaf(qA1, x.y, qA0 * x.x));
            float sB = fmaf(qB2, x.z, fmaf(qB1, x.y, qB0 * x.x));
            float pA = ex2f(sA) * ((j <= rowA) ? MASK_E : 1.0f);
            float pB = ex2f(sB) * ((j <= rowB) ? MASK_E : 1.0f);
            lA += pA; aA0 = fmaf(pA, x.x, aA0); aA1 = fmaf(pA, x.y, aA1); aA2 = fmaf(pA, x.z, aA2);
            lB += pB; aB0 = fmaf(pB, x.x, aB0); aB1 = fmaf(pB, x.y, aB1); aB2 = fmaf(pB, x.z, aB2);
        }
        s_U[128 + rowA*4 + q4] = make_float4(lA, aA0, aA1, aA2);
        s_U[128 + rowB*4 + q4] = make_float4(lB, aB0, aB1, aB2);
    }
    __syncthreads();
    if (t < SPR) {
        float4 p0 = s_U[128 + t*4], p1 = s_U[128 + t*4 + 1];
        float4 p2 = s_U[128 + t*4 + 2], p3 = s_U[128 + t*4 + 3];
        float4 xt = s_U[t];
        float inv = rcpf(p0.x + p1.x + p2.x + p3.x);
        float v0, v1, v2;
        proj3(P.dec_a1_in_w + 18, P.dec_a1_in_b + 6,
              (p0.y+p1.y+p2.y+p3.y)*inv, (p0.z+p1.z+p2.z+p3.z)*inv, (p0.w+p1.w+p2.w+p3.w)*inv,
              v0, v1, v2);
        float r0, r1, r2;
        proj3(P.dec_a1_out_w, P.dec_a1_out_b, v0, v1, v2, r0, r1, r2);
        s_R[t*3+0] = r0 + xt.x;
        s_R[t*3+1] = r1 + xt.y;
        s_R[t*3+2] = r2 + xt.z;
    }
    __syncthreads();
    layer_norm(s_R, s_x2, SPR, INV384, P.dec_ln1_w, P.dec_ln1_b, s_red);

    // D3: cross keys = raw enc_out rows -> s_U[0..256)
    s_U[t] = make_float4(s_E[t*3], s_E[t*3+1], s_E[t*3+2], 0.f);
    __syncthreads();

    // D4: cross-attn. 2 queries {r64, r64+64} x 64 keys (quarter q4).
    {
        int rowA = r64, rowB = r64 + 64;
        float qA0,qA1,qA2, qB0,qB1,qB2;
        make_q(P.dec_a2_in_w, P.dec_a2_in_b, s_x2[rowA*3], s_x2[rowA*3+1], s_x2[rowA*3+2], qA0,qA1,qA2);
        make_q(P.dec_a2_in_w, P.dec_a2_in_b, s_x2[rowB*3], s_x2[rowB*3+1], s_x2[rowB*3+2], qB0,qB1,qB2);
        float lA=0.f,aA0=0.f,aA1=0.f,aA2=0.f;
        float lB=0.f,aB0=0.f,aB1=0.f,aB2=0.f;
        int j0 = q4 * 64;
        #pragma unroll 4
        for (int j = j0; j < j0 + 64; ++j) {
            float4 x = s_U[j];
            float sA = fmaf(qA2, x.z, fmaf(qA1, x.y, qA0 * x.x));
            float sB = fmaf(qB2, x.z, fmaf(qB1, x.y, qB0 * x.x));
            float pA = ex2f(sA), pB = ex2f(sB);
            lA += pA; aA0 = fmaf(pA, x.x, aA0); aA1 = fmaf(pA, x.y, aA1); aA2 = fmaf(pA, x.z, aA2);
            lB += pB; aB0 = fmaf(pB, x.x, aB0); aB1 = fmaf(pB, x.y, aB1); aB2 = fmaf(pB, x.z, aB2);
        }
        s_U[256 + rowA*4 + q4] = make_float4(lA, aA0, aA1, aA2);
        s_U[256 + rowB*4 + q4] = make_float4(lB, aB0, aB1, aB2);
    }
    __syncthreads();
    if (t < SPR) {
        float4 p0 = s_U[256 + t*4], p1 = s_U[256 + t*4 + 1];
        float4 p2 = s_U[256 + t*4 + 2], p3 = s_U[256 + t*4 + 3];
        float inv = rcpf(p0.x + p1.x + p2.x + p3.x);
        float v0, v1, v2;
        proj3(P.dec_a2_in_w + 18, P.dec_a2_in_b + 6,
              (p0.y+p1.y+p2.y+p3.y)*inv, (p0.z+p1.z+p2.z+p3.z)*inv, (p0.w+p1.w+p2.w+p3.w)*inv,
              v0, v1, v2);
        float r0, r1, r2;
        proj3(P.dec_a2_out_w, P.dec_a2_out_b, v0, v1, v2, r0, r1, r2);
        s_R[t*3+0] = r0 + s_x2[t*3+0];
        s_R[t*3+1] = r1 + s_x2[t*3+1];
        s_R[t*3+2] = r2 + s_x2[t*3+2];
    }
    __syncthreads();
    layer_norm(s_R, s_x2, SPR, INV384, P.dec_ln1_w, P.dec_ln1_b, s_red);  // x3

    // D5: dec FFN. 2 rows {r64, r64+64} x 128 hidden (quarter q4).
    // Partials: q4 0,1 -> s_R[q4*384 + ...], q4 2,3 -> s_E[(q4-2)*384 + ...]
    load_wff(s_U, P.dec_lin1_w, P.dec_lin1_b, P.dec_lin2_w);
    {
        int rowA = r64, rowB = r64 + 64;
        float xA0=s_x2[rowA*3], xA1=s_x2[rowA*3+1], xA2=s_x2[rowA*3+2];
        float xB0=s_x2[rowB*3], xB1=s_x2[rowB*3+1], xB2=s_x2[rowB*3+2];
        float aA0=0.f,aA1=0.f,aA2=0.f, aB0=0.f,aB1=0.f,aB2=0.f;
        int h0 = q4 * 128;
        #pragma unroll 4
        for (int h = h0; h < h0 + 128; ++h) {
            float4 w1 = s_U[2*h];
            float4 w2 = s_U[2*h+1];
            float tA = fmaxf(fmaf(w1.x, xA0, fmaf(w1.y, xA1, fmaf(w1.z, xA2, w1.w))), 0.f);
            float tB = fmaxf(fmaf(w1.x, xB0, fmaf(w1.y, xB1, fmaf(w1.z, xB2, w1.w))), 0.f);
            aA0 = fmaf(tA, w2.x, aA0); aA1 = fmaf(tA, w2.y, aA1); aA2 = fmaf(tA, w2.z, aA2);
            aB0 = fmaf(tB, w2.x, aB0); aB1 = fmaf(tB, w2.y, aB1); aB2 = fmaf(tB, w2.z, aB2);
        }
        float* dst = (q4 < 2) ? s_R : s_E;
        int off = (q4 & 1) * 384;
        dst[off + rowA*3+0]=aA0; dst[off + rowA*3+1]=aA1; dst[off + rowA*3+2]=aA2;
        dst[off + rowB*3+0]=aB0; dst[off + rowB*3+1]=aB1; dst[off + rowB*3+2]=aB2;
    }
    __syncthreads();
    if (t < SPR) {
        float db0 = P.dec_lin2_b[0], db1 = P.dec_lin2_b[1], db2 = P.dec_lin2_b[2];
        s_R[t*3+0] = s_R[t*3+0] + s_R[384+t*3+0] + s_E[t*3+0] + s_E[384+t*3+0] + db0 + s_x2[t*3+0];
        s_R[t*3+1] = s_R[t*3+1] + s_R[384+t*3+1] + s_E[t*3+1] + s_E[384+t*3+1] + db1 + s_x2[t*3+1];
        s_R[t*3+2] = s_R[t*3+2] + s_R[384+t*3+2] + s_E[t*3+2] + s_E[384+t*3+2] + db2 + s_x2[t*3+2];
    }
    __syncthreads();
    layer_norm_out(s_R, P.out + (size_t)b * SPR * 3, SPR, INV384,
                   P.dec_ln3_w, P.dec_ln3_b, s_red);
}

extern "C" void kernel_launch(void* const* d_in, const int* in_sizes, int n_in,
                              void* d_out, int out_size) {
    (void)in_sizes; (void)n_in; (void)out_size;
    Params P;
    P.X            = (const float*)d_in[0];
    P.T            = (const float*)d_in[1];
    P.enc_in_w     = (const float*)d_in[2];
    P.enc_in_b     = (const float*)d_in[3];
    P.enc_out_w    = (const float*)d_in[4];
    P.enc_out_b    = (const float*)d_in[5];
    P.enc_ln1_w    = (const float*)d_in[6];
    P.enc_ln1_b    = (const float*)d_in[7];
    P.enc_lin1_w   = (const float*)d_in[8];
    P.enc_lin1_b   = (const float*)d_in[9];
    P.enc_lin2_w   = (const float*)d_in[10];
    P.enc_lin2_b   = (const float*)d_in[11];
    P.enc_ln2_w    = (const float*)d_in[12];
    P.enc_ln2_b    = (const float*)d_in[13];
    P.dec_a1_in_w  = (const float*)d_in[14];
    P.dec_a1_in_b  = (const float*)d_in[15];
    P.dec_a1_out_w = (const float*)d_in[16];
    P.dec_a1_out_b = (const float*)d_in[17];
    P.dec_ln1_w    = (const float*)d_in[18];
    P.dec_ln1_b    = (const float*)d_in[19];
    P.dec_a2_in_w  = (const float*)d_in[20];
    P.dec_a2_in_b  = (const float*)d_in[21];
    P.dec_a2_out_w = (const float*)d_in[22];
    P.dec_a2_out_b = (const float*)d_in[23];
    P.dec_lin1_w   = (const float*)d_in[24];
    P.dec_lin1_b   = (const float*)d_in[25];
    P.dec_lin2_w   = (const float*)d_in[26];
    P.dec_lin2_b   = (const float*)d_in[27];
    P.dec_ln3_w    = (const float*)d_in[28];
    P.dec_ln3_b    = (const float*)d_in[29];
    P.out          = (float*)d_out;

    fused_transformer_kernel<<<NB, 256>>>(P);
}

// round 6
// speedup vs baseline: 2.0038x; 1.0379x over previous
#include <cuda_runtime.h>
#include <math.h>

#define NB    1024
#define SIN   256
#define SPR   128
#define HIDN  512

// 1/sqrt(3) * log2(e): fold scores into exp2 domain
#define C_SCALE 0.83294064f
// log2(e): additive causal "mask" of +1.0 in exp2 domain
#define L2E 1.4426950408889634f

typedef unsigned long long u64;

struct Params {
    const float* X;           const float* T;
    const float* enc_in_w;    const float* enc_in_b;
    const float* enc_out_w;   const float* enc_out_b;
    const float* enc_ln1_w;   const float* enc_ln1_b;
    const float* enc_lin1_w;  const float* enc_lin1_b;
    const float* enc_lin2_w;  const float* enc_lin2_b;
    const float* enc_ln2_w;   const float* enc_ln2_b;
    const float* dec_a1_in_w; const float* dec_a1_in_b;
    const float* dec_a1_out_w;const float* dec_a1_out_b;
    const float* dec_ln1_w;   const float* dec_ln1_b;
    const float* dec_a2_in_w; const float* dec_a2_in_b;
    const float* dec_a2_out_w;const float* dec_a2_out_b;
    const float* dec_lin1_w;  const float* dec_lin1_b;
    const float* dec_lin2_w;  const float* dec_lin2_b;
    const float* dec_ln3_w;   const float* dec_ln3_b;
    float* out;
};

__device__ __forceinline__ float ex2f(float x) {
    float y; asm("ex2.approx.ftz.f32 %0, %1;" : "=f"(y) : "f"(x)); return y;
}
__device__ __forceinline__ float rcpf(float x) {
    float y; asm("rcp.approx.ftz.f32 %0, %1;" : "=f"(y) : "f"(x)); return y;
}

// ---- packed f32x2 ops (Blackwell) ----
__device__ __forceinline__ u64 fma2(u64 a, u64 b, u64 c) {
    u64 d; asm("fma.rn.f32x2 %0, %1, %2, %3;" : "=l"(d) : "l"(a), "l"(b), "l"(c)); return d;
}
__device__ __forceinline__ u64 mul2(u64 a, u64 b) {
    u64 d; asm("mul.rn.f32x2 %0, %1, %2;" : "=l"(d) : "l"(a), "l"(b)); return d;
}
__device__ __forceinline__ u64 add2(u64 a, u64 b) {
    u64 d; asm("add.rn.f32x2 %0, %1, %2;" : "=l"(d) : "l"(a), "l"(b)); return d;
}
__device__ __forceinline__ u64 pack2(float lo, float hi) {
    u64 d; asm("mov.b64 %0, {%1, %2};" : "=l"(d) : "f"(lo), "f"(hi)); return d;
}
__device__ __forceinline__ void unpack2(u64 d, float& a, float& b) {
    asm("mov.b64 {%0, %1}, %2;" : "=f"(a), "=f"(b) : "l"(d));
}

// One packed attention step: 2 keys vs 1 query. l folded into packed add.
__device__ __forceinline__ void qstep(u64 q0p, u64 q1p, u64 q2p,
                                      u64 xp, u64 yp, u64 zp,
                                      u64& aX, u64& aY, u64& aZ, u64& aL) {
    u64 d = fma2(q2p, zp, fma2(q1p, yp, mul2(q0p, xp)));
    float s0, s1; unpack2(d, s0, s1);
    u64 pp = pack2(ex2f(s0), ex2f(s1));
    aX = fma2(pp, xp, aX);
    aY = fma2(pp, yp, aY);
    aZ = fma2(pp, zp, aZ);
    aL = add2(aL, pp);
}
// Masked variant: reference ADDS tril(ones) to scores -> +log2(e) in exp2 domain.
__device__ __forceinline__ void qstep_m(u64 q0p, u64 q1p, u64 q2p,
                                        u64 xp, u64 yp, u64 zp,
                                        int j, int row,
                                        u64& aX, u64& aY, u64& aZ, u64& aL) {
    u64 d = fma2(q2p, zp, fma2(q1p, yp, mul2(q0p, xp)));
    float s0, s1; unpack2(d, s0, s1);
    s0 += (j     <= row) ? L2E : 0.f;
    s1 += (j + 1 <= row) ? L2E : 0.f;
    u64 pp = pack2(ex2f(s0), ex2f(s1));
    aX = fma2(pp, xp, aX);
    aY = fma2(pp, yp, aY);
    aZ = fma2(pp, zp, aZ);
    aL = add2(aL, pp);
}
__device__ __forceinline__ void hsum4(u64 aX, u64 aY, u64 aZ, u64 aL,
                                      float& x, float& y, float& z, float& l) {
    float a, b;
    unpack2(aX, a, b); x = a + b;
    unpack2(aY, a, b); y = a + b;
    unpack2(aZ, a, b); z = a + b;
    unpack2(aL, a, b); l = a + b;
}

// Fused two-value block reduction (2 barriers).
__device__ __forceinline__ void block_sum2(float& a, float& b, float* red) {
    #pragma unroll
    for (int o = 16; o; o >>= 1) {
        a += __shfl_xor_sync(0xffffffffu, a, o);
        b += __shfl_xor_sync(0xffffffffu, b, o);
    }
    int w = threadIdx.x >> 5;
    if ((threadIdx.x & 31) == 0) { red[w] = a; red[8 + w] = b; }
    __syncthreads();
    if (threadIdx.x < 16) {
        float x = red[threadIdx.x];
        x += __shfl_xor_sync(0x0000ffffu, x, 4);
        x += __shfl_xor_sync(0x0000ffffu, x, 2);
        x += __shfl_xor_sync(0x0000ffffu, x, 1);
        if ((threadIdx.x & 7) == 0) red[16 + (threadIdx.x >> 3)] = x;
    }
    __syncthreads();
    a = red[16]; b = red[17];
}

// LN over nrows*3 elems jointly; var = E[x^2]-mean^2 single pass.
__device__ __forceinline__ void layer_norm(const float* src, float* dst, int nrows,
                                           float inv_n, const float* w, const float* bb,
                                           float* red) {
    int t = threadIdx.x;
    float x0 = 0.f, x1 = 0.f, x2 = 0.f;
    if (t < nrows) { x0 = src[t*3]; x1 = src[t*3+1]; x2 = src[t*3+2]; }
    float s1 = x0 + x1 + x2;
    float s2 = fmaf(x0, x0, fmaf(x1, x1, x2 * x2));
    block_sum2(s1, s2, red);
    float mean = s1 * inv_n;
    float var  = fmaf(-mean, mean, s2 * inv_n);
    float rs = rsqrtf(var + 1e-5f);
    if (t < nrows) {
        dst[t*3+0] = (x0 - mean) * rs * w[t*3+0] + bb[t*3+0];
        dst[t*3+1] = (x1 - mean) * rs * w[t*3+1] + bb[t*3+1];
        dst[t*3+2] = (x2 - mean) * rs * w[t*3+2] + bb[t*3+2];
    }
    __syncthreads();
}

// LN writing into SoA arrays (for cross-attn keys).
__device__ __forceinline__ void layer_norm_soa(const float* src,
                                               float* dX, float* dY, float* dZ, int nrows,
                                               float inv_n, const float* w, const float* bb,
                                               float* red) {
    int t = threadIdx.x;
    float x0 = 0.f, x1 = 0.f, x2 = 0.f;
    if (t < nrows) { x0 = src[t*3]; x1 = src[t*3+1]; x2 = src[t*3+2]; }
    float s1 = x0 + x1 + x2;
    float s2 = fmaf(x0, x0, fmaf(x1, x1, x2 * x2));
    block_sum2(s1, s2, red);
    float mean = s1 * inv_n;
    float var  = fmaf(-mean, mean, s2 * inv_n);
    float rs = rsqrtf(var + 1e-5f);
    if (t < nrows) {
        dX[t] = (x0 - mean) * rs * w[t*3+0] + bb[t*3+0];
        dY[t] = (x1 - mean) * rs * w[t*3+1] + bb[t*3+1];
        dZ[t] = (x2 - mean) * rs * w[t*3+2] + bb[t*3+2];
    }
    __syncthreads();
}

// Final LN -> global.
__device__ __forceinline__ void layer_norm_out(const float* src, float* gout, int nrows,
                                               float inv_n, const float* w, const float* bb,
                                               float* red) {
    int t = threadIdx.x;
    float x0 = 0.f, x1 = 0.f, x2 = 0.f;
    if (t < nrows) { x0 = src[t*3]; x1 = src[t*3+1]; x2 = src[t*3+2]; }
    float s1 = x0 + x1 + x2;
    float s2 = fmaf(x0, x0, fmaf(x1, x1, x2 * x2));
    block_sum2(s1, s2, red);
    float mean = s1 * inv_n;
    float var  = fmaf(-mean, mean, s2 * inv_n);
    float rs = rsqrtf(var + 1e-5f);
    if (t < nrows) {
        gout[t*3+0] = (x0 - mean) * rs * w[t*3+0] + bb[t*3+0];
        gout[t*3+1] = (x1 - mean) * rs * w[t*3+1] + bb[t*3+1];
        gout[t*3+2] = (x2 - mean) * rs * w[t*3+2] + bb[t*3+2];
    }
}

__device__ __forceinline__ void proj3(const float* w, const float* bias,
                                      float x0, float x1, float x2,
                                      float& o0, float& o1, float& o2) {
    o0 = fmaf(w[0], x0, fmaf(w[1], x1, fmaf(w[2], x2, bias[0])));
    o1 = fmaf(w[3], x0, fmaf(w[4], x1, fmaf(w[5], x2, bias[1])));
    o2 = fmaf(w[6], x0, fmaf(w[7], x1, fmaf(w[8], x2, bias[2])));
}
__device__ __forceinline__ void proj3T(const float* w,
                                       float x0, float x1, float x2,
                                       float& o0, float& o1, float& o2) {
    o0 = fmaf(w[0], x0, fmaf(w[3], x1, w[6] * x2));
    o1 = fmaf(w[1], x0, fmaf(w[4], x1, w[7] * x2));
    o2 = fmaf(w[2], x0, fmaf(w[5], x1, w[8] * x2));
}
// q' = (Wk^T (Wq x + bq)) * C_SCALE; bk dropped (cancels in softmax)
__device__ __forceinline__ void make_q(const float* in_w, const float* in_b,
                                       float x0, float x1, float x2,
                                       float& q0, float& q1, float& q2) {
    float t0, t1, t2;
    proj3(in_w, in_b, x0, x1, x2, t0, t1, t2);
    proj3T(in_w + 9, t0, t1, t2, q0, q1, q2);
    q0 *= C_SCALE; q1 *= C_SCALE; q2 *= C_SCALE;
}

__device__ __forceinline__ void load_wff(float4* s_wff, const float* w1, const float* b1,
                                         const float* w2) {
    for (int h = threadIdx.x; h < HIDN; h += 256) {
        s_wff[2*h]   = make_float4(w1[h*3], w1[h*3+1], w1[h*3+2], b1[h]);
        s_wff[2*h+1] = make_float4(w2[h], w2[HIDN + h], w2[2*HIDN + h], 0.f);
    }
    __syncthreads();
}

// pos_enc row s: first 3 sin columns, invf[e] = 10000^(-2e/256)
__device__ __forceinline__ void pos3(int s, float& p0, float& p1, float& p2) {
    const float f1 = (float)0.93057204868496882;  // 10000^(-2/256)
    const float f2 = (float)0.86596432336006538;  // 10000^(-4/256)
    float a0 = (float)s;
    p0 = sinf(a0);
    p1 = sinf(a0 * f1);
    p2 = sinf(a0 * f2);
}

// One CTA = one batch. Grid caps occupancy at ~7 CTAs/SM -> allow 36 regs.
__global__ void __launch_bounds__(256, 7)
fused_transformer_kernel(Params P) {
    // 16KB union s_U, time-multiplexed:
    //   attn: SoA keys (enc: sf[0..768), pT: sf[768..1152)) + partials s_U[320..576)
    //   ffn:  packed weights (2 float4 per h) over s_U[0..1024)
    __shared__ __align__(16) float4 s_U[1024];
    __shared__ float s_x2[SIN * 3];
    __shared__ float s_R[SIN * 3];
    __shared__ float s_E[SIN * 3];
    __shared__ float s_red[18];

    float* const sf = (float*)s_U;
    float* const sX = sf;            // 256 floats
    float* const sY = sf + 256;
    float* const sZ = sf + 512;
    float* const pX = sf + 768;      // 128 floats (pT keys)
    float* const pY = sf + 896;
    float* const pZ = sf + 1024;
    float4* const s_part = s_U + 320;  // 256 float4 partials

    const int b    = blockIdx.x;
    const int t    = threadIdx.x;
    const int r128 = t & 127, half2 = t >> 7;
    const float INV768 = 1.0f / 768.0f;
    const float INV384 = 1.0f / 384.0f;

    float pe0, pe1, pe2;
    pos3(t, pe0, pe1, pe2);

    // ================= ENCODER =================
    // E1: pX = X + pos_enc -> SoA keys
    {
        const float* xr = P.X + ((size_t)b * SIN + t) * 3;
        sX[t] = xr[0] + pe0;
        sY[t] = xr[1] + pe1;
        sZ[t] = xr[2] + pe2;
    }
    __syncthreads();

    // E2: self-attention. 1 query (row t) x all 256 keys, packed f32x2.
    {
        float x0 = sX[t], x1 = sY[t], x2v = sZ[t];
        float q0, q1, q2;
        make_q(P.enc_in_w, P.enc_in_b, x0, x1, x2v, q0, q1, q2);
        u64 q0p = pack2(q0, q0), q1p = pack2(q1, q1), q2p = pack2(q2, q2);
        u64 aX = 0, aY = 0, aZ = 0, aL = 0;
        const double2* X2 = (const double2*)sX;
        const double2* Y2 = (const double2*)sY;
        const double2* Z2 = (const double2*)sZ;
        #pragma unroll 4
        for (int i = 0; i < 64; ++i) {
            double2 dx = X2[i], dy = Y2[i], dz = Z2[i];
            qstep(q0p, q1p, q2p,
                  __double_as_longlong(dx.x), __double_as_longlong(dy.x), __double_as_longlong(dz.x),
                  aX, aY, aZ, aL);
            qstep(q0p, q1p, q2p,
                  __double_as_longlong(dx.y), __double_as_longlong(dy.y), __double_as_longlong(dz.y),
                  aX, aY, aZ, aL);
        }
        float ax, ay, az, l;
        hsum4(aX, aY, aZ, aL, ax, ay, az, l);
        float inv = rcpf(l);
        float v0, v1, v2;
        proj3(P.enc_in_w + 18, P.enc_in_b + 6, ax*inv, ay*inv, az*inv, v0, v1, v2);
        float r0, r1, r2;
        proj3(P.enc_out_w, P.enc_out_b, v0, v1, v2, r0, r1, r2);
        s_R[t*3+0] = r0 + x0;
        s_R[t*3+1] = r1 + x1;
        s_R[t*3+2] = r2 + x2v;
    }
    __syncthreads();
    layer_norm(s_R, s_x2, SIN, INV768, P.enc_ln1_w, P.enc_ln1_b, s_red);

    // E3: FFN. 2 rows {r128, r128+128} x 256 hidden (half2 split).
    load_wff(s_U, P.enc_lin1_w, P.enc_lin1_b, P.enc_lin2_w);
    {
        int rowA = r128, rowB = r128 + 128;
        float xA0=s_x2[rowA*3], xA1=s_x2[rowA*3+1], xA2=s_x2[rowA*3+2];
        float xB0=s_x2[rowB*3], xB1=s_x2[rowB*3+1], xB2=s_x2[rowB*3+2];
        float aA0=0.f,aA1=0.f,aA2=0.f, aB0=0.f,aB1=0.f,aB2=0.f;
        int h0 = half2 * 256;
        #pragma unroll 4
        for (int h = h0; h < h0 + 256; ++h) {
            float4 w1 = s_U[2*h];
            float4 w2 = s_U[2*h+1];
            float tA = fmaxf(fmaf(w1.x, xA0, fmaf(w1.y, xA1, fmaf(w1.z, xA2, w1.w))), 0.f);
            float tB = fmaxf(fmaf(w1.x, xB0, fmaf(w1.y, xB1, fmaf(w1.z, xB2, w1.w))), 0.f);
            aA0 = fmaf(tA, w2.x, aA0); aA1 = fmaf(tA, w2.y, aA1); aA2 = fmaf(tA, w2.z, aA2);
            aB0 = fmaf(tB, w2.x, aB0); aB1 = fmaf(tB, w2.y, aB1); aB2 = fmaf(tB, w2.z, aB2);
        }
        float* dst = half2 ? s_R : s_E;
        dst[rowA*3+0]=aA0; dst[rowA*3+1]=aA1; dst[rowA*3+2]=aA2;
        dst[rowB*3+0]=aB0; dst[rowB*3+1]=aB1; dst[rowB*3+2]=aB2;
    }
    __syncthreads();
    {
        float eb0 = P.enc_lin2_b[0], eb1 = P.enc_lin2_b[1], eb2 = P.enc_lin2_b[2];
        s_R[t*3+0] = s_E[t*3+0] + s_R[t*3+0] + eb0 + s_x2[t*3+0];
        s_R[t*3+1] = s_E[t*3+1] + s_R[t*3+1] + eb1 + s_x2[t*3+1];
        s_R[t*3+2] = s_E[t*3+2] + s_R[t*3+2] + eb2 + s_x2[t*3+2];
    }
    __syncthreads();
    // LN2 -> enc_out straight into SoA key arrays (for cross-attn)
    layer_norm_soa(s_R, sX, sY, sZ, SIN, INV768, P.enc_ln2_w, P.enc_ln2_b, s_red);

    // ================= DECODER =================
    // D1: pT -> SoA (pX/pY/pZ)
    if (t < SPR) {
        const float* tr = P.T + ((size_t)b * SPR + t) * 3;
        pX[t] = tr[0] + pe0;
        pY[t] = tr[1] + pe1;
        pZ[t] = tr[2] + pe2;
    }
    __syncthreads();

    // D2: dec self-attn. query r128, keys [half2*64, +64), causal +1 mask.
    {
        int row = r128;
        float x0 = pX[row], x1 = pY[row], x2v = pZ[row];
        float q0, q1, q2;
        make_q(P.dec_a1_in_w, P.dec_a1_in_b, x0, x1, x2v, q0, q1, q2);
        u64 q0p = pack2(q0, q0), q1p = pack2(q1, q1), q2p = pack2(q2, q2);
        u64 aX = 0, aY = 0, aZ = 0, aL = 0;
        const double2* X2 = (const double2*)pX;
        const double2* Y2 = (const double2*)pY;
        const double2* Z2 = (const double2*)pZ;
        int i0 = half2 * 16;
        #pragma unroll 4
        for (int i = i0; i < i0 + 16; ++i) {
            int j = i * 4;
            double2 dx = X2[i], dy = Y2[i], dz = Z2[i];
            qstep_m(q0p, q1p, q2p,
                    __double_as_longlong(dx.x), __double_as_longlong(dy.x), __double_as_longlong(dz.x),
                    j, row, aX, aY, aZ, aL);
            qstep_m(q0p, q1p, q2p,
                    __double_as_longlong(dx.y), __double_as_longlong(dy.y), __double_as_longlong(dz.y),
                    j + 2, row, aX, aY, aZ, aL);
        }
        float ax, ay, az, l;
        hsum4(aX, aY, aZ, aL, ax, ay, az, l);
        s_part[row*2 + half2] = make_float4(l, ax, ay, az);
    }
    __syncthreads();
    if (t < SPR) {
        float4 pa = s_part[t*2], pb = s_part[t*2+1];
        float inv = rcpf(pa.x + pb.x);
        float v0, v1, v2;
        proj3(P.dec_a1_in_w + 18, P.dec_a1_in_b + 6,
              (pa.y+pb.y)*inv, (pa.z+pb.z)*inv, (pa.w+pb.w)*inv, v0, v1, v2);
        float r0, r1, r2;
        proj3(P.dec_a1_out_w, P.dec_a1_out_b, v0, v1, v2, r0, r1, r2);
        s_R[t*3+0] = r0 + pX[t];
        s_R[t*3+1] = r1 + pY[t];
        s_R[t*3+2] = r2 + pZ[t];
    }
    __syncthreads();
    layer_norm(s_R, s_x2, SPR, INV384, P.dec_ln1_w, P.dec_ln1_b, s_red);

    // D4: cross-attn. query r128 (x2), keys = enc_out SoA [half2*128, +128).
    {
        int row = r128;
        float q0, q1, q2;
        make_q(P.dec_a2_in_w, P.dec_a2_in_b,
               s_x2[row*3], s_x2[row*3+1], s_x2[row*3+2], q0, q1, q2);
        u64 q0p = pack2(q0, q0), q1p = pack2(q1, q1), q2p = pack2(q2, q2);
        u64 aX = 0, aY = 0, aZ = 0, aL = 0;
        const double2* X2 = (const double2*)sX;
        const double2* Y2 = (const double2*)sY;
        const double2* Z2 = (const double2*)sZ;
        int i0 = half2 * 32;
        #pragma unroll 4
        for (int i = i0; i < i0 + 32; ++i) {
            double2 dx = X2[i], dy = Y2[i], dz = Z2[i];
            qstep(q0p, q1p, q2p,
                  __double_as_longlong(dx.x), __double_as_longlong(dy.x), __double_as_longlong(dz.x),
                  aX, aY, aZ, aL);
            qstep(q0p, q1p, q2p,
                  __double_as_longlong(dx.y), __double_as_longlong(dy.y), __double_as_longlong(dz.y),
                  aX, aY, aZ, aL);
        }
        float ax, ay, az, l;
        hsum4(aX, aY, aZ, aL, ax, ay, az, l);
        s_part[row*2 + half2] = make_float4(l, ax, ay, az);
    }
    __syncthreads();
    if (t < SPR) {
        float4 pa = s_part[t*2], pb = s_part[t*2+1];
        float inv = rcpf(pa.x + pb.x);
        float v0, v1, v2;
        proj3(P.dec_a2_in_w + 18, P.dec_a2_in_b + 6,
              (pa.y+pb.y)*inv, (pa.z+pb.z)*inv, (pa.w+pb.w)*inv, v0, v1, v2);
        float r0, r1, r2;
        proj3(P.dec_a2_out_w, P.dec_a2_out_b, v0, v1, v2, r0, r1, r2);
        s_R[t*3+0] = r0 + s_x2[t*3+0];
        s_R[t*3+1] = r1 + s_x2[t*3+1];
        s_R[t*3+2] = r2 + s_x2[t*3+2];
    }
    __syncthreads();
    layer_norm(s_R, s_x2, SPR, INV384, P.dec_ln1_w, P.dec_ln1_b, s_red);  // x3

    // D5: dec FFN. 2 rows {r64, r64+64} x 128 hidden (q4 split).
    load_wff(s_U, P.dec_lin1_w, P.dec_lin1_b, P.dec_lin2_w);
    {
        const int r64 = t & 63, q4 = t >> 6;
        int rowA = r64, rowB = r64 + 64;
        float xA0=s_x2[rowA*3], xA1=s_x2[rowA*3+1], xA2=s_x2[rowA*3+2];
        float xB0=s_x2[rowB*3], xB1=s_x2[rowB*3+1], xB2=s_x2[rowB*3+2];
        float aA0=0.f,aA1=0.f,aA2=0.f, aB0=0.f,aB1=0.f,aB2=0.f;
        int h0 = q4 * 128;
        #pragma unroll 4
        for (int h = h0; h < h0 + 128; ++h) {
            float4 w1 = s_U[2*h];
            float4 w2 = s_U[2*h+1];
            float tA = fmaxf(fmaf(w1.x, xA0, fmaf(w1.y, xA1, fmaf(w1.z, xA2, w1.w))), 0.f);
            float tB = fmaxf(fmaf(w1.x, xB0, fmaf(w1.y, xB1, fmaf(w1.z, xB2, w1.w))), 0.f);
            aA0 = fmaf(tA, w2.x, aA0); aA1 = fmaf(tA, w2.y, aA1); aA2 = fmaf(tA, w2.z, aA2);
            aB0 = fmaf(tB, w2.x, aB0); aB1 = fmaf(tB, w2.y, aB1); aB2 = fmaf(tB, w2.z, aB2);
        }
        float* dst = (q4 < 2) ? s_R : s_E;
        int off = (q4 & 1) * 384;
        dst[off + rowA*3+0]=aA0; dst[off + rowA*3+1]=aA1; dst[off + rowA*3+2]=aA2;
        dst[off + rowB*3+0]=aB0; dst[off + rowB*3+1]=aB1; dst[off + rowB*3+2]=aB2;
    }
    __syncthreads();
    if (t < SPR) {
        float db0 = P.dec_lin2_b[0], db1 = P.dec_lin2_b[1], db2 = P.dec_lin2_b[2];
        s_R[t*3+0] = s_R[t*3+0] + s_R[384+t*3+0] + s_E[t*3+0] + s_E[384+t*3+0] + db0 + s_x2[t*3+0];
        s_R[t*3+1] = s_R[t*3+1] + s_R[384+t*3+1] + s_E[t*3+1] + s_E[384+t*3+1] + db1 + s_x2[t*3+1];
        s_R[t*3+2] = s_R[t*3+2] + s_R[384+t*3+2] + s_E[t*3+2] + s_E[384+t*3+2] + db2 + s_x2[t*3+2];
    }
    __syncthreads();
    layer_norm_out(s_R, P.out + (size_t)b * SPR * 3, SPR, INV384,
                   P.dec_ln3_w, P.dec_ln3_b, s_red);
}

extern "C" void kernel_launch(void* const* d_in, const int* in_sizes, int n_in,
                              void* d_out, int out_size) {
    (void)in_sizes; (void)n_in; (void)out_size;
    Params P;
    P.X            = (const float*)d_in[0];
    P.T            = (const float*)d_in[1];
    P.enc_in_w     = (const float*)d_in[2];
    P.enc_in_b     = (const float*)d_in[3];
    P.enc_out_w    = (const float*)d_in[4];
    P.enc_out_b    = (const float*)d_in[5];
    P.enc_ln1_w    = (const float*)d_in[6];
    P.enc_ln1_b    = (const float*)d_in[7];
    P.enc_lin1_w   = (const float*)d_in[8];
    P.enc_lin1_b   = (const float*)d_in[9];
    P.enc_lin2_w   = (const float*)d_in[10];
    P.enc_lin2_b   = (const float*)d_in[11];
    P.enc_ln2_w    = (const float*)d_in[12];
    P.enc_ln2_b    = (const float*)d_in[13];
    P.dec_a1_in_w  = (const float*)d_in[14];
    P.dec_a1_in_b  = (const float*)d_in[15];
    P.dec_a1_out_w = (const float*)d_in[16];
    P.dec_a1_out_b = (const float*)d_in[17];
    P.dec_ln1_w    = (const float*)d_in[18];
    P.dec_ln1_b    = (const float*)d_in[19];
    P.dec_a2_in_w  = (const float*)d_in[20];
    P.dec_a2_in_b  = (const float*)d_in[21];
    P.dec_a2_out_w = (const float*)d_in[22];
    P.dec_a2_out_b = (const float*)d_in[23];
    P.dec_lin1_w   = (const float*)d_in[24];
    P.dec_lin1_b   = (const float*)d_in[25];
    P.dec_lin2_w   = (const float*)d_in[26];
    P.dec_lin2_b   = (const float*)d_in[27];
    P.dec_ln3_w    = (const float*)d_in[28];
    P.dec_ln3_b    = (const float*)d_in[29];
    P.out          = (float*)d_out;

    fused_transformer_kernel<<<NB, 256>>>(P);
}